// round 1
// baseline (speedup 1.0000x reference)
#include <cuda_runtime.h>
#include <math.h>

// Problem constants
#define BN   4
#define SN   512
#define DN   64
#define HN   8
#define FFN  128
#define EPSV 1e-5f

// ---------------------------------------------------------------------------
// Scratch (device globals; no allocation allowed)
// ---------------------------------------------------------------------------
__device__ float g_q[BN * HN * SN * DN];          // 4 MB   [b,h,s,d]
__device__ float g_k[BN * HN * SN * DN];          // 4 MB
__device__ float g_v[BN * HN * SN * DN];          // 4 MB
__device__ float g_p[(size_t)BN * HN * SN * SN];  // 33.5MB [b,h,i,j]
__device__ float g_heads[BN * SN * HN * DN];      // 4 MB   [b,s, h*64+d]
__device__ float g_x[BN * SN * DN];               // 0.5MB  post-LN1 activations

// ---------------------------------------------------------------------------
// Kernel 1: QKV projection.  [2048 x 64] @ [64 x 512] for each of Wq/Wk/Wv.
// Output written head-major: g_{q,k,v}[((b*8+h)*512 + s)*64 + dd].
// Tile 64x64, 256 threads, 4x4 microtile. N-tile == one head (64 cols).
// ---------------------------------------------------------------------------
__global__ __launch_bounds__(256) void qkv_kernel(
    const float* __restrict__ seq, const float* __restrict__ Wq,
    const float* __restrict__ Wk, const float* __restrict__ Wv)
{
    __shared__ float sA[64][65];
    __shared__ float sB[64][65];
    const int m0   = blockIdx.x * 64;   // global row tile (b*512 + s)
    const int head = blockIdx.y;        // 0..7
    const float* __restrict__ W =
        (blockIdx.z == 0) ? Wq : (blockIdx.z == 1 ? Wk : Wv);
    float* outB = (blockIdx.z == 0) ? g_q : (blockIdx.z == 1 ? g_k : g_v);
    const int tid = threadIdx.x;

    for (int idx = tid; idx < 64 * 16; idx += 256) {
        int r = idx >> 4, c = (idx & 15) << 2;
        float4 a4 = *reinterpret_cast<const float4*>(seq + (size_t)(m0 + r) * 64 + c);
        sA[r][c] = a4.x; sA[r][c + 1] = a4.y; sA[r][c + 2] = a4.z; sA[r][c + 3] = a4.w;
        float4 b4 = *reinterpret_cast<const float4*>(W + (size_t)r * 512 + head * 64 + c);
        sB[r][c] = b4.x; sB[r][c + 1] = b4.y; sB[r][c + 2] = b4.z; sB[r][c + 3] = b4.w;
    }
    __syncthreads();

    const int ty = tid >> 4, tx = tid & 15;
    float acc[4][4] = {};
    #pragma unroll 16
    for (int k = 0; k < 64; k++) {
        float a[4], b[4];
        #pragma unroll
        for (int i = 0; i < 4; i++) a[i] = sA[ty * 4 + i][k];
        #pragma unroll
        for (int j = 0; j < 4; j++) b[j] = sB[k][tx * 4 + j];
        #pragma unroll
        for (int i = 0; i < 4; i++)
            #pragma unroll
            for (int j = 0; j < 4; j++)
                acc[i][j] += a[i] * b[j];
    }

    const int bb = m0 >> 9;         // batch (tile never straddles b: 512 % 64 == 0)
    const int s0 = m0 & 511;
    #pragma unroll
    for (int i = 0; i < 4; i++) {
        float4 o4 = make_float4(acc[i][0], acc[i][1], acc[i][2], acc[i][3]);
        *reinterpret_cast<float4*>(
            outB + ((size_t)((bb * HN + head) * SN + s0 + ty * 4 + i)) * DN + tx * 4) = o4;
    }
}

// ---------------------------------------------------------------------------
// Kernel 2: positional bias  p[b,h,i,j] = pos_enc[b,i,j,:]·Wp[:,h] + bp[h].
// Streams pos_enc (268 MB) exactly once. Block = 128 consecutive j for one
// (b,i). Writes are coalesced 512B runs per head.
// ---------------------------------------------------------------------------
__global__ __launch_bounds__(128) void posbias_kernel(
    const float* __restrict__ pos, const float* __restrict__ Wp,
    const float* __restrict__ bp)
{
    __shared__ float sP[128][65];
    __shared__ float sW[64][8];
    __shared__ float sbp[8];
    const int jt  = blockIdx.x;  // 0..3
    const int i   = blockIdx.y;  // 0..511
    const int b   = blockIdx.z;  // 0..3
    const int tid = threadIdx.x; // 0..127

    for (int idx = tid; idx < 512; idx += 128) sW[idx >> 3][idx & 7] = Wp[idx];
    if (tid < 8) sbp[tid] = bp[tid];

    const float* src = pos + (((size_t)b * SN + i) * SN + jt * 128) * DN;
    for (int idx = tid; idx < 128 * 16; idx += 128) {
        int r = idx >> 4, c = (idx & 15) << 2;
        float4 v4 = *reinterpret_cast<const float4*>(src + (size_t)r * 64 + c);
        sP[r][c] = v4.x; sP[r][c + 1] = v4.y; sP[r][c + 2] = v4.z; sP[r][c + 3] = v4.w;
    }
    __syncthreads();

    float acc[8];
    #pragma unroll
    for (int h = 0; h < 8; h++) acc[h] = sbp[h];
    #pragma unroll 16
    for (int d = 0; d < 64; d++) {
        float x = sP[tid][d];
        #pragma unroll
        for (int h = 0; h < 8; h++) acc[h] += x * sW[d][h];
    }

    const int j = jt * 128 + tid;
    #pragma unroll
    for (int h = 0; h < 8; h++)
        g_p[(((size_t)b * HN + h) * SN + i) * SN + j] = acc[h];
}

// ---------------------------------------------------------------------------
// Kernel 3: attention for one (b,h) and a 64-row i-tile.
// Full 512-wide score row held in smem -> exact softmax, no rescale passes.
// smem (dynamic, 165,888 B): sQ[64][65] | sKV[64][65] | sS[64][517] | sInv[64]
// ---------------------------------------------------------------------------
#define SQ_LD 65
#define SS_LD 517
#define ATTN_SMEM_BYTES ((64 * SQ_LD * 2 + 64 * SS_LD + 64) * 4)

__global__ __launch_bounds__(256) void attn_kernel()
{
    extern __shared__ float sm[];
    float* sQ   = sm;
    float* sKV  = sQ + 64 * SQ_LD;
    float* sS   = sKV + 64 * SQ_LD;
    float* sInv = sS + 64 * SS_LD;

    const int bh  = blockIdx.x;        // b*8 + h
    const int i0  = blockIdx.y * 64;
    const int tid = threadIdx.x;
    const int ty = tid >> 4, tx = tid & 15;
    const int lane = tid & 31, warp = tid >> 5;

    // Q tile
    const float* qsrc = g_q + ((size_t)bh * SN + i0) * DN;
    for (int idx = tid; idx < 64 * 16; idx += 256) {
        int r = idx >> 4, c = (idx & 15) << 2;
        float4 v4 = *reinterpret_cast<const float4*>(qsrc + (size_t)r * 64 + c);
        sQ[r * SQ_LD + c]     = v4.x; sQ[r * SQ_LD + c + 1] = v4.y;
        sQ[r * SQ_LD + c + 2] = v4.z; sQ[r * SQ_LD + c + 3] = v4.w;
    }
    const float* pbase = g_p + ((size_t)bh * SN + i0) * SN;

    // Phase 1: S = QK^T * 0.125 + P
    for (int jt = 0; jt < 8; jt++) {
        __syncthreads();
        const float* ksrc = g_k + ((size_t)bh * SN + jt * 64) * DN;
        for (int idx = tid; idx < 64 * 16; idx += 256) {
            int r = idx >> 4, c = (idx & 15) << 2;
            float4 v4 = *reinterpret_cast<const float4*>(ksrc + (size_t)r * 64 + c);
            sKV[r * SQ_LD + c]     = v4.x; sKV[r * SQ_LD + c + 1] = v4.y;
            sKV[r * SQ_LD + c + 2] = v4.z; sKV[r * SQ_LD + c + 3] = v4.w;
        }
        __syncthreads();
        float acc[4][4] = {};
        #pragma unroll 16
        for (int k = 0; k < 64; k++) {
            float a[4], b[4];
            #pragma unroll
            for (int i = 0; i < 4; i++) a[i] = sQ[(ty * 4 + i) * SQ_LD + k];
            #pragma unroll
            for (int j = 0; j < 4; j++) b[j] = sKV[(tx * 4 + j) * SQ_LD + k];
            #pragma unroll
            for (int i = 0; i < 4; i++)
                #pragma unroll
                for (int j = 0; j < 4; j++)
                    acc[i][j] += a[i] * b[j];
        }
        #pragma unroll
        for (int i = 0; i < 4; i++) {
            float4 pv = *reinterpret_cast<const float4*>(
                pbase + (size_t)(ty * 4 + i) * SN + jt * 64 + tx * 4);
            float* srow = sS + (ty * 4 + i) * SS_LD + jt * 64 + tx * 4;
            srow[0] = acc[i][0] * 0.125f + pv.x;
            srow[1] = acc[i][1] * 0.125f + pv.y;
            srow[2] = acc[i][2] * 0.125f + pv.z;
            srow[3] = acc[i][3] * 0.125f + pv.w;
        }
    }
    __syncthreads();

    // Phase 2: softmax (unnormalized; 1/sum applied at output)
    for (int r = warp; r < 64; r += 8) {
        float* row = sS + r * SS_LD;
        float mx = -1e30f;
        for (int c = lane; c < 512; c += 32) mx = fmaxf(mx, row[c]);
        #pragma unroll
        for (int off = 16; off > 0; off >>= 1)
            mx = fmaxf(mx, __shfl_xor_sync(0xffffffffu, mx, off));
        float sum = 0.f;
        for (int c = lane; c < 512; c += 32) {
            float e = __expf(row[c] - mx);
            row[c] = e;
            sum += e;
        }
        #pragma unroll
        for (int off = 16; off > 0; off >>= 1)
            sum += __shfl_xor_sync(0xffffffffu, sum, off);
        if (lane == 0) sInv[r] = 1.f / sum;
    }

    // Phase 3: O = P_softmax @ V
    float o[4][4] = {};
    for (int jt = 0; jt < 8; jt++) {
        __syncthreads();
        const float* vsrc = g_v + ((size_t)bh * SN + jt * 64) * DN;
        for (int idx = tid; idx < 64 * 16; idx += 256) {
            int r = idx >> 4, c = (idx & 15) << 2;
            float4 v4 = *reinterpret_cast<const float4*>(vsrc + (size_t)r * 64 + c);
            sKV[r * SQ_LD + c]     = v4.x; sKV[r * SQ_LD + c + 1] = v4.y;
            sKV[r * SQ_LD + c + 2] = v4.z; sKV[r * SQ_LD + c + 3] = v4.w;
        }
        __syncthreads();
        #pragma unroll 16
        for (int k = 0; k < 64; k++) {
            float a[4], b[4];
            #pragma unroll
            for (int i = 0; i < 4; i++) a[i] = sS[(ty * 4 + i) * SS_LD + jt * 64 + k];
            #pragma unroll
            for (int j = 0; j < 4; j++) b[j] = sKV[k * SQ_LD + tx * 4 + j];
            #pragma unroll
            for (int i = 0; i < 4; i++)
                #pragma unroll
                for (int j = 0; j < 4; j++)
                    o[i][j] += a[i] * b[j];
        }
    }

    const int b_ = bh >> 3, h_ = bh & 7;
    #pragma unroll
    for (int i = 0; i < 4; i++) {
        float inv = sInv[ty * 4 + i];
        float4 o4 = make_float4(o[i][0] * inv, o[i][1] * inv, o[i][2] * inv, o[i][3] * inv);
        *reinterpret_cast<float4*>(
            g_heads + ((size_t)(b_ * SN + i0 + ty * 4 + i)) * (HN * DN) + h_ * 64 + tx * 4) = o4;
    }
}

// ---------------------------------------------------------------------------
// Kernel 4a: o = heads @ Wo ; x = LN(seq + o) * g_att + b_att  -> g_x
// Tile 64 rows x 64 cols (full d row -> LN can fuse), K=512 in 8 chunks.
// ---------------------------------------------------------------------------
__global__ __launch_bounds__(256) void proj_ln_kernel(
    const float* __restrict__ seq, const float* __restrict__ Wo,
    const float* __restrict__ gam, const float* __restrict__ bet)
{
    __shared__ float sA[64][65];   // heads chunk, reused as x after GEMM
    __shared__ float sB[64][65];   // Wo chunk
    const int m0  = blockIdx.x * 64;
    const int tid = threadIdx.x;
    const int ty = tid >> 4, tx = tid & 15;

    float acc[4][4] = {};
    for (int kc = 0; kc < 8; kc++) {
        __syncthreads();
        for (int idx = tid; idx < 64 * 16; idx += 256) {
            int r = idx >> 4, c = (idx & 15) << 2;
            float4 a4 = *reinterpret_cast<const float4*>(
                g_heads + (size_t)(m0 + r) * 512 + kc * 64 + c);
            sA[r][c] = a4.x; sA[r][c + 1] = a4.y; sA[r][c + 2] = a4.z; sA[r][c + 3] = a4.w;
            float4 b4 = *reinterpret_cast<const float4*>(
                Wo + (size_t)(kc * 64 + r) * 64 + c);
            sB[r][c] = b4.x; sB[r][c + 1] = b4.y; sB[r][c + 2] = b4.z; sB[r][c + 3] = b4.w;
        }
        __syncthreads();
        #pragma unroll 16
        for (int k = 0; k < 64; k++) {
            float a[4], b[4];
            #pragma unroll
            for (int i = 0; i < 4; i++) a[i] = sA[ty * 4 + i][k];
            #pragma unroll
            for (int j = 0; j < 4; j++) b[j] = sB[k][tx * 4 + j];
            #pragma unroll
            for (int i = 0; i < 4; i++)
                #pragma unroll
                for (int j = 0; j < 4; j++)
                    acc[i][j] += a[i] * b[j];
        }
    }
    __syncthreads();

    // x = acc + seq  (reuse sA)
    #pragma unroll
    for (int i = 0; i < 4; i++) {
        float4 sv = *reinterpret_cast<const float4*>(
            seq + (size_t)(m0 + ty * 4 + i) * 64 + tx * 4);
        sA[ty * 4 + i][tx * 4 + 0] = acc[i][0] + sv.x;
        sA[ty * 4 + i][tx * 4 + 1] = acc[i][1] + sv.y;
        sA[ty * 4 + i][tx * 4 + 2] = acc[i][2] + sv.z;
        sA[ty * 4 + i][tx * 4 + 3] = acc[i][3] + sv.w;
    }
    __syncthreads();

    const int lane = tid & 31, warp = tid >> 5;
    for (int r = warp; r < 64; r += 8) {
        float x0 = sA[r][lane], x1 = sA[r][lane + 32];
        float s = x0 + x1, ss = x0 * x0 + x1 * x1;
        #pragma unroll
        for (int off = 16; off > 0; off >>= 1) {
            s  += __shfl_xor_sync(0xffffffffu, s, off);
            ss += __shfl_xor_sync(0xffffffffu, ss, off);
        }
        float mu  = s * (1.f / 64.f);
        float var = ss * (1.f / 64.f) - mu * mu;
        float rs  = rsqrtf(var + EPSV);
        g_x[(size_t)(m0 + r) * 64 + lane]      = (x0 - mu) * rs * gam[lane] + bet[lane];
        g_x[(size_t)(m0 + r) * 64 + lane + 32] = (x1 - mu) * rs * gam[lane + 32] + bet[lane + 32];
    }
}

// ---------------------------------------------------------------------------
// Kernel 4b: y = relu(x@W1+b1)@W2+b2 ; out = LN(x+y)*g_ff + b_ff
// 2 rows per block (256 threads, 128 per row). W1/W2 stay L1-resident.
// ---------------------------------------------------------------------------
__global__ __launch_bounds__(256) void ffn_ln_kernel(
    const float* __restrict__ W1, const float* __restrict__ b1,
    const float* __restrict__ W2, const float* __restrict__ b2,
    const float* __restrict__ gam, const float* __restrict__ bet,
    float* __restrict__ out)
{
    __shared__ float sX[2][64];
    __shared__ float sY[2][128];
    __shared__ float sZ[2][64];
    const int tid  = threadIdx.x;
    const int half = tid >> 7;          // 0/1: which row
    const int t    = tid & 127;
    const size_t row = (size_t)blockIdx.x * 2 + half;

    if (t < 64) sX[half][t] = g_x[row * 64 + t];
    __syncthreads();

    float a1 = b1[t];
    #pragma unroll 16
    for (int d = 0; d < 64; d++) a1 += sX[half][d] * W1[d * 128 + t];
    sY[half][t] = fmaxf(a1, 0.f);
    __syncthreads();

    if (t < 64) {
        float a2 = b2[t];
        #pragma unroll 16
        for (int f = 0; f < 128; f++) a2 += sY[half][f] * W2[f * 64 + t];
        sZ[half][t] = sX[half][t] + a2;
    }
    __syncthreads();

    if (t < 32) {  // lanes 0..31 of warp0 (half 0) / warp4 (half 1): full warps
        float z0 = sZ[half][t], z1 = sZ[half][t + 32];
        float s = z0 + z1, ss = z0 * z0 + z1 * z1;
        #pragma unroll
        for (int off = 16; off > 0; off >>= 1) {
            s  += __shfl_xor_sync(0xffffffffu, s, off);
            ss += __shfl_xor_sync(0xffffffffu, ss, off);
        }
        float mu  = s * (1.f / 64.f);
        float var = ss * (1.f / 64.f) - mu * mu;
        float rs  = rsqrtf(var + EPSV);
        out[row * 64 + t]      = (z0 - mu) * rs * gam[t] + bet[t];
        out[row * 64 + t + 32] = (z1 - mu) * rs * gam[t + 32] + bet[t + 32];
    }
}

// ---------------------------------------------------------------------------
// Launch
// ---------------------------------------------------------------------------
extern "C" void kernel_launch(void* const* d_in, const int* in_sizes, int n_in,
                              void* d_out, int out_size)
{
    const float* seq   = (const float*)d_in[0];
    const float* pos   = (const float*)d_in[1];
    const float* Wq    = (const float*)d_in[2];
    const float* Wk    = (const float*)d_in[3];
    const float* Wv    = (const float*)d_in[4];
    const float* Wo    = (const float*)d_in[5];
    const float* Wp    = (const float*)d_in[6];
    const float* bp    = (const float*)d_in[7];
    const float* W1    = (const float*)d_in[8];
    const float* b1    = (const float*)d_in[9];
    const float* W2    = (const float*)d_in[10];
    const float* b2    = (const float*)d_in[11];
    const float* g_att = (const float*)d_in[12];
    const float* b_att = (const float*)d_in[13];
    const float* g_ff  = (const float*)d_in[14];
    const float* b_ff  = (const float*)d_in[15];
    float* outp = (float*)d_out;

    cudaFuncSetAttribute(attn_kernel, cudaFuncAttributeMaxDynamicSharedMemorySize,
                         ATTN_SMEM_BYTES);

    qkv_kernel<<<dim3(32, 8, 3), 256>>>(seq, Wq, Wk, Wv);
    posbias_kernel<<<dim3(4, 512, 4), 128>>>(pos, Wp, bp);
    attn_kernel<<<dim3(32, 8), 256, ATTN_SMEM_BYTES>>>();
    proj_ln_kernel<<<32, 256>>>(seq, Wo, g_att, b_att);
    ffn_ln_kernel<<<1024, 256>>>(W1, b1, W2, b2, g_ff, b_ff, outp);
}

// round 2
// speedup vs baseline: 1.1313x; 1.1313x over previous
#include <cuda_runtime.h>
#include <math.h>

// Problem constants
#define BN   4
#define SN   512
#define DN   64
#define HN   8
#define FFN  128
#define EPSV 1e-5f

typedef unsigned long long u64;

// ---------------------------------------------------------------------------
// Packed fp32x2 helpers (Blackwell sm_100+): 2 IEEE fp32 FMAs per instruction.
// ---------------------------------------------------------------------------
__device__ __forceinline__ u64 pack2(float lo, float hi) {
    u64 r; asm("mov.b64 %0, {%1, %2};" : "=l"(r) : "f"(lo), "f"(hi)); return r;
}
__device__ __forceinline__ u64 dup2(float x) {
    u64 r; asm("mov.b64 %0, {%1, %1};" : "=l"(r) : "f"(x)); return r;
}
__device__ __forceinline__ void ffma2(u64& d, u64 a, u64 b) {
    asm("fma.rn.f32x2 %0, %1, %2, %0;" : "+l"(d) : "l"(a), "l"(b));
}
__device__ __forceinline__ float2 unpack2(u64 v) {
    float2 f; asm("mov.b64 {%0, %1}, %2;" : "=f"(f.x), "=f"(f.y) : "l"(v)); return f;
}

// ---------------------------------------------------------------------------
// Scratch (device globals; no allocation allowed)
// ---------------------------------------------------------------------------
__device__ float g_q[BN * HN * SN * DN];          // 4 MB   [b,h,s,d]
__device__ float g_k[BN * HN * SN * DN];          // 4 MB
__device__ float g_v[BN * HN * SN * DN];          // 4 MB
__device__ float g_p[(size_t)BN * HN * SN * SN];  // 33.5MB [b,h,i,j]
__device__ float g_heads[BN * SN * HN * DN];      // 4 MB   [b,s, h*64+d]
__device__ float g_x[BN * SN * DN];               // 0.5MB  post-LN1 activations

// ---------------------------------------------------------------------------
// Kernel 1: QKV projection.  [2048 x 64] @ [64 x 512] for each of Wq/Wk/Wv.
// 64x64 tile, 256 threads, 4x4 microtile, FFMA2 inner (pairs along j).
// ---------------------------------------------------------------------------
__global__ __launch_bounds__(256) void qkv_kernel(
    const float* __restrict__ seq, const float* __restrict__ Wq,
    const float* __restrict__ Wk, const float* __restrict__ Wv)
{
    __shared__ float sA[64 * 65];
    __shared__ float sB[64 * 66];
    const int m0   = blockIdx.x * 64;
    const int head = blockIdx.y;
    const float* __restrict__ W =
        (blockIdx.z == 0) ? Wq : (blockIdx.z == 1 ? Wk : Wv);
    float* outB = (blockIdx.z == 0) ? g_q : (blockIdx.z == 1 ? g_k : g_v);
    const int tid = threadIdx.x;

    for (int idx = tid; idx < 64 * 16; idx += 256) {
        int r = idx >> 4, c = (idx & 15) << 2;
        float4 a4 = *reinterpret_cast<const float4*>(seq + (size_t)(m0 + r) * 64 + c);
        sA[r * 65 + c] = a4.x; sA[r * 65 + c + 1] = a4.y;
        sA[r * 65 + c + 2] = a4.z; sA[r * 65 + c + 3] = a4.w;
        float4 b4 = *reinterpret_cast<const float4*>(W + (size_t)r * 512 + head * 64 + c);
        sB[r * 66 + c] = b4.x; sB[r * 66 + c + 1] = b4.y;
        sB[r * 66 + c + 2] = b4.z; sB[r * 66 + c + 3] = b4.w;
    }
    __syncthreads();

    const int ty = tid >> 4, tx = tid & 15;
    u64 acc[4][2] = {};
    #pragma unroll 16
    for (int k = 0; k < 64; k++) {
        u64 b0 = *reinterpret_cast<const u64*>(&sB[k * 66 + tx * 4]);
        u64 b1 = *reinterpret_cast<const u64*>(&sB[k * 66 + tx * 4 + 2]);
        #pragma unroll
        for (int i = 0; i < 4; i++) {
            u64 a = dup2(sA[(ty * 4 + i) * 65 + k]);
            ffma2(acc[i][0], a, b0);
            ffma2(acc[i][1], a, b1);
        }
    }

    const int bb = m0 >> 9;
    const int s0 = m0 & 511;
    #pragma unroll
    for (int i = 0; i < 4; i++) {
        float2 p0 = unpack2(acc[i][0]), p1 = unpack2(acc[i][1]);
        float4 o4 = make_float4(p0.x, p0.y, p1.x, p1.y);
        *reinterpret_cast<float4*>(
            outB + ((size_t)((bb * HN + head) * SN + s0 + ty * 4 + i)) * DN + tx * 4) = o4;
    }
}

// ---------------------------------------------------------------------------
// Kernel 2: positional bias  p[b,h,i,j] = pos_enc[b,i,j,:]·Wp[:,h] + bp[h].
// Streams pos_enc (268 MB) once; HBM-floor bound.
// ---------------------------------------------------------------------------
__global__ __launch_bounds__(128) void posbias_kernel(
    const float* __restrict__ pos, const float* __restrict__ Wp,
    const float* __restrict__ bp)
{
    __shared__ float sP[128][65];
    __shared__ float sW[64][8];
    __shared__ float sbp[8];
    const int jt  = blockIdx.x;
    const int i   = blockIdx.y;
    const int b   = blockIdx.z;
    const int tid = threadIdx.x;

    for (int idx = tid; idx < 512; idx += 128) sW[idx >> 3][idx & 7] = Wp[idx];
    if (tid < 8) sbp[tid] = bp[tid];

    const float* src = pos + (((size_t)b * SN + i) * SN + jt * 128) * DN;
    #pragma unroll
    for (int it = 0; it < 16; it++) {
        int idx = tid + it * 128;
        int r = idx >> 4, c = (idx & 15) << 2;
        float4 v4 = *reinterpret_cast<const float4*>(src + (size_t)r * 64 + c);
        sP[r][c] = v4.x; sP[r][c + 1] = v4.y; sP[r][c + 2] = v4.z; sP[r][c + 3] = v4.w;
    }
    __syncthreads();

    u64 acc[4];
    #pragma unroll
    for (int hp = 0; hp < 4; hp++) acc[hp] = pack2(sbp[2 * hp], sbp[2 * hp + 1]);
    #pragma unroll 16
    for (int d = 0; d < 64; d++) {
        u64 x = dup2(sP[tid][d]);
        #pragma unroll
        for (int hp = 0; hp < 4; hp++) {
            u64 w = *reinterpret_cast<const u64*>(&sW[d][2 * hp]);
            ffma2(acc[hp], x, w);
        }
    }

    const int j = jt * 128 + tid;
    #pragma unroll
    for (int hp = 0; hp < 4; hp++) {
        float2 v = unpack2(acc[hp]);
        g_p[(((size_t)b * HN + 2 * hp) * SN + i) * SN + j]     = v.x;
        g_p[(((size_t)b * HN + 2 * hp + 1) * SN + i) * SN + j] = v.y;
    }
}

// ---------------------------------------------------------------------------
// Kernel 3: attention; one (b,h) x 32-row i-tile per block. 91.4KB smem ->
// 2 CTAs/SM. FFMA2 inner loops; K tile transposed in smem so the j-operand
// is contiguous (LDS.64 pairs); V stays row-major (d contiguous).
// smem: sQ[32][65] | sKV[64][66] | sS[32][516] | sInv[32]
// ---------------------------------------------------------------------------
#define TI      32
#define SQLD    65
#define KVLD    66
#define SSLD    516
#define ATTN_SMEM_FLOATS (TI * SQLD + 64 * KVLD + TI * SSLD + TI)
#define ATTN_SMEM_BYTES  (ATTN_SMEM_FLOATS * 4)

__global__ __launch_bounds__(256) void attn_kernel()
{
    extern __shared__ float sm[];
    float* sQ   = sm;                       // [32][65]  row-major Q
    float* sKV  = sQ + TI * SQLD;           // [64][66]  K^T (phase1) / V (phase3)
    float* sS   = sKV + 64 * KVLD;          // [32][516] scores
    float* sInv = sS + TI * SSLD;

    const int bh  = blockIdx.x;             // b*8 + h
    const int i0  = blockIdx.y * TI;
    const int tid = threadIdx.x;
    const int ty = tid >> 4, tx = tid & 15;
    const int lane = tid & 31, warp = tid >> 5;

    // Q tile (row-major)
    const float* qsrc = g_q + ((size_t)bh * SN + i0) * DN;
    #pragma unroll
    for (int it = 0; it < 2; it++) {
        int idx = tid + it * 256;
        int r = idx >> 4, c = (idx & 15) << 2;
        float4 v = *reinterpret_cast<const float4*>(qsrc + (size_t)r * 64 + c);
        sQ[r * SQLD + c] = v.x; sQ[r * SQLD + c + 1] = v.y;
        sQ[r * SQLD + c + 2] = v.z; sQ[r * SQLD + c + 3] = v.w;
    }
    const float* pbase = g_p + ((size_t)bh * SN + i0) * SN;

    // Phase 1: S = QK^T * 0.125 + P   (K transposed into sKV[k][j])
    for (int jt = 0; jt < 8; jt++) {
        __syncthreads();
        const float* ksrc = g_k + ((size_t)bh * SN + jt * 64) * DN;
        #pragma unroll
        for (int it = 0; it < 4; it++) {
            int idx = tid + it * 256;
            int r = idx >> 4, c = (idx & 15) << 2;   // r = key row (j), c = d
            float4 v = *reinterpret_cast<const float4*>(ksrc + (size_t)r * 64 + c);
            sKV[(c + 0) * KVLD + r] = v.x;
            sKV[(c + 1) * KVLD + r] = v.y;
            sKV[(c + 2) * KVLD + r] = v.z;
            sKV[(c + 3) * KVLD + r] = v.w;
        }
        __syncthreads();
        u64 acc[2][2] = {};                 // [i in {0,1}][j-pair]
        #pragma unroll 16
        for (int k = 0; k < 64; k++) {
            u64 b0 = *reinterpret_cast<const u64*>(&sKV[k * KVLD + tx * 4]);
            u64 b1 = *reinterpret_cast<const u64*>(&sKV[k * KVLD + tx * 4 + 2]);
            u64 a0 = dup2(sQ[(ty * 2 + 0) * SQLD + k]);
            u64 a1 = dup2(sQ[(ty * 2 + 1) * SQLD + k]);
            ffma2(acc[0][0], a0, b0); ffma2(acc[0][1], a0, b1);
            ffma2(acc[1][0], a1, b0); ffma2(acc[1][1], a1, b1);
        }
        #pragma unroll
        for (int i = 0; i < 2; i++) {
            float2 p01 = unpack2(acc[i][0]), p23 = unpack2(acc[i][1]);
            float4 pv = *reinterpret_cast<const float4*>(
                pbase + (size_t)(ty * 2 + i) * SN + jt * 64 + tx * 4);
            float4 o = make_float4(p01.x * 0.125f + pv.x, p01.y * 0.125f + pv.y,
                                   p23.x * 0.125f + pv.z, p23.y * 0.125f + pv.w);
            *reinterpret_cast<float4*>(&sS[(ty * 2 + i) * SSLD + jt * 64 + tx * 4]) = o;
        }
    }
    __syncthreads();

    // Phase 2: softmax (unnormalized; 1/sum folded into output)
    for (int r = warp; r < TI; r += 8) {
        float* row = sS + r * SSLD;
        float mx = -1e30f;
        for (int c = lane; c < 512; c += 32) mx = fmaxf(mx, row[c]);
        #pragma unroll
        for (int off = 16; off > 0; off >>= 1)
            mx = fmaxf(mx, __shfl_xor_sync(0xffffffffu, mx, off));
        float sum = 0.f;
        for (int c = lane; c < 512; c += 32) {
            float e = __expf(row[c] - mx);
            row[c] = e;
            sum += e;
        }
        #pragma unroll
        for (int off = 16; off > 0; off >>= 1)
            sum += __shfl_xor_sync(0xffffffffu, sum, off);
        if (lane == 0) sInv[r] = 1.f / sum;
    }

    // Phase 3: O = P @ V  (V row-major: d contiguous)
    u64 o2[2][2] = {};
    for (int jt = 0; jt < 8; jt++) {
        __syncthreads();
        const float* vsrc = g_v + ((size_t)bh * SN + jt * 64) * DN;
        #pragma unroll
        for (int it = 0; it < 4; it++) {
            int idx = tid + it * 256;
            int r = idx >> 4, c = (idx & 15) << 2;
            float4 v = *reinterpret_cast<const float4*>(vsrc + (size_t)r * 64 + c);
            sKV[r * KVLD + c] = v.x; sKV[r * KVLD + c + 1] = v.y;
            sKV[r * KVLD + c + 2] = v.z; sKV[r * KVLD + c + 3] = v.w;
        }
        __syncthreads();
        #pragma unroll 16
        for (int k = 0; k < 64; k++) {
            u64 b0 = *reinterpret_cast<const u64*>(&sKV[k * KVLD + tx * 4]);
            u64 b1 = *reinterpret_cast<const u64*>(&sKV[k * KVLD + tx * 4 + 2]);
            u64 a0 = dup2(sS[(ty * 2 + 0) * SSLD + jt * 64 + k]);
            u64 a1 = dup2(sS[(ty * 2 + 1) * SSLD + jt * 64 + k]);
            ffma2(o2[0][0], a0, b0); ffma2(o2[0][1], a0, b1);
            ffma2(o2[1][0], a1, b0); ffma2(o2[1][1], a1, b1);
        }
    }

    const int b_ = bh >> 3, h_ = bh & 7;
    #pragma unroll
    for (int i = 0; i < 2; i++) {
        float inv = sInv[ty * 2 + i];
        float2 p01 = unpack2(o2[i][0]), p23 = unpack2(o2[i][1]);
        float4 o4 = make_float4(p01.x * inv, p01.y * inv, p23.x * inv, p23.y * inv);
        *reinterpret_cast<float4*>(
            g_heads + ((size_t)(b_ * SN + i0 + ty * 2 + i)) * (HN * DN) + h_ * 64 + tx * 4) = o4;
    }
}

// ---------------------------------------------------------------------------
// Kernel 4a: o = heads @ Wo ; x = LN(seq + o) -> g_x.
// 16-row tiles -> grid 128 (was 32: occupancy starved at 42us).
// ---------------------------------------------------------------------------
__global__ __launch_bounds__(256) void proj_ln_kernel(
    const float* __restrict__ seq, const float* __restrict__ Wo,
    const float* __restrict__ gam, const float* __restrict__ bet)
{
    __shared__ float sA[16 * 65];
    __shared__ float sB[64 * 66];
    const int m0  = blockIdx.x * 16;
    const int tid = threadIdx.x;
    const int ty = tid >> 4, tx = tid & 15;    // ty = row 0..15, tx*4 = col

    u64 acc[2] = {};
    for (int kc = 0; kc < 8; kc++) {
        __syncthreads();
        {   // heads tile: 16 x 64 (one float4 per thread)
            int r = tid >> 4, c = (tid & 15) << 2;
            float4 a4 = *reinterpret_cast<const float4*>(
                g_heads + (size_t)(m0 + r) * 512 + kc * 64 + c);
            sA[r * 65 + c] = a4.x; sA[r * 65 + c + 1] = a4.y;
            sA[r * 65 + c + 2] = a4.z; sA[r * 65 + c + 3] = a4.w;
        }
        #pragma unroll
        for (int it = 0; it < 4; it++) {       // Wo tile: 64 x 64
            int idx = tid + it * 256;
            int r = idx >> 4, c = (idx & 15) << 2;
            float4 b4 = *reinterpret_cast<const float4*>(
                Wo + (size_t)(kc * 64 + r) * 64 + c);
            sB[r * 66 + c] = b4.x; sB[r * 66 + c + 1] = b4.y;
            sB[r * 66 + c + 2] = b4.z; sB[r * 66 + c + 3] = b4.w;
        }
        __syncthreads();
        #pragma unroll 16
        for (int k = 0; k < 64; k++) {
            u64 a = dup2(sA[ty * 65 + k]);
            u64 b0 = *reinterpret_cast<const u64*>(&sB[k * 66 + tx * 4]);
            u64 b1 = *reinterpret_cast<const u64*>(&sB[k * 66 + tx * 4 + 2]);
            ffma2(acc[0], a, b0);
            ffma2(acc[1], a, b1);
        }
    }
    __syncthreads();

    {   // x = acc + seq (reuse sA as [16][65])
        float2 p0 = unpack2(acc[0]), p1 = unpack2(acc[1]);
        float4 sv = *reinterpret_cast<const float4*>(
            seq + (size_t)(m0 + ty) * 64 + tx * 4);
        sA[ty * 65 + tx * 4 + 0] = p0.x + sv.x;
        sA[ty * 65 + tx * 4 + 1] = p0.y + sv.y;
        sA[ty * 65 + tx * 4 + 2] = p1.x + sv.z;
        sA[ty * 65 + tx * 4 + 3] = p1.y + sv.w;
    }
    __syncthreads();

    const int lane = tid & 31, warp = tid >> 5;
    for (int r = warp; r < 16; r += 8) {
        float x0 = sA[r * 65 + lane], x1 = sA[r * 65 + lane + 32];
        float s = x0 + x1, ss = x0 * x0 + x1 * x1;
        #pragma unroll
        for (int off = 16; off > 0; off >>= 1) {
            s  += __shfl_xor_sync(0xffffffffu, s, off);
            ss += __shfl_xor_sync(0xffffffffu, ss, off);
        }
        float mu  = s * (1.f / 64.f);
        float var = ss * (1.f / 64.f) - mu * mu;
        float rs  = rsqrtf(var + EPSV);
        g_x[(size_t)(m0 + r) * 64 + lane]      = (x0 - mu) * rs * gam[lane] + bet[lane];
        g_x[(size_t)(m0 + r) * 64 + lane + 32] = (x1 - mu) * rs * gam[lane + 32] + bet[lane + 32];
    }
}

// ---------------------------------------------------------------------------
// Kernel 4b: y = relu(x@W1+b1)@W2+b2 ; out = LN(x+y).
// 4 rows/block, 64 threads/row, FFMA2 with LDG.64 weight pairs.
// ---------------------------------------------------------------------------
__global__ __launch_bounds__(256) void ffn_ln_kernel(
    const float* __restrict__ W1, const float* __restrict__ b1,
    const float* __restrict__ W2, const float* __restrict__ b2,
    const float* __restrict__ gam, const float* __restrict__ bet,
    float* __restrict__ out)
{
    __shared__ float sX[4][64];
    __shared__ float sY[4][128];
    __shared__ float sPp[4][64];
    __shared__ float sZ[4][64];
    const int tid  = threadIdx.x;
    const int r4   = tid >> 6;          // row within block (0..3)
    const int t    = tid & 63;
    const size_t row = (size_t)blockIdx.x * 4 + r4;

    sX[r4][t] = g_x[row * 64 + t];
    __syncthreads();

    // GEMM1: thread t computes hidden pair (2t, 2t+1)
    u64 a1 = *reinterpret_cast<const u64*>(b1 + 2 * t);
    #pragma unroll 16
    for (int d = 0; d < 64; d++) {
        u64 w = *reinterpret_cast<const u64*>(W1 + (size_t)d * 128 + 2 * t);
        ffma2(a1, dup2(sX[r4][d]), w);
    }
    {
        float2 y = unpack2(a1);
        sY[r4][2 * t]     = fmaxf(y.x, 0.f);
        sY[r4][2 * t + 1] = fmaxf(y.y, 0.f);
    }
    __syncthreads();

    // GEMM2: group g covers f in [64g, 64g+64); thread computes d-pair (2u, 2u+1)
    const int u = t & 31, g = t >> 5;
    u64 a2 = 0;                         // bit pattern (0.0f, 0.0f)
    #pragma unroll 16
    for (int f = 0; f < 64; f++) {
        u64 w = *reinterpret_cast<const u64*>(W2 + (size_t)(g * 64 + f) * 64 + 2 * u);
        ffma2(a2, dup2(sY[r4][g * 64 + f]), w);
    }
    float2 p = unpack2(a2);
    if (g == 1) { sPp[r4][2 * u] = p.x; sPp[r4][2 * u + 1] = p.y; }
    __syncthreads();
    if (g == 0) {
        sZ[r4][2 * u]     = p.x + sPp[r4][2 * u]     + b2[2 * u]     + sX[r4][2 * u];
        sZ[r4][2 * u + 1] = p.y + sPp[r4][2 * u + 1] + b2[2 * u + 1] + sX[r4][2 * u + 1];
    }
    __syncthreads();

    if (g == 0) {                       // one full warp per row (tids r4*64 .. +31)
        float z0 = sZ[r4][u], z1 = sZ[r4][u + 32];
        float s = z0 + z1, ss = z0 * z0 + z1 * z1;
        #pragma unroll
        for (int off = 16; off > 0; off >>= 1) {
            s  += __shfl_xor_sync(0xffffffffu, s, off);
            ss += __shfl_xor_sync(0xffffffffu, ss, off);
        }
        float mu  = s * (1.f / 64.f);
        float var = ss * (1.f / 64.f) - mu * mu;
        float rs  = rsqrtf(var + EPSV);
        out[row * 64 + u]      = (z0 - mu) * rs * gam[u] + bet[u];
        out[row * 64 + u + 32] = (z1 - mu) * rs * gam[u + 32] + bet[u + 32];
    }
}

// ---------------------------------------------------------------------------
// Launch
// ---------------------------------------------------------------------------
extern "C" void kernel_launch(void* const* d_in, const int* in_sizes, int n_in,
                              void* d_out, int out_size)
{
    const float* seq   = (const float*)d_in[0];
    const float* pos   = (const float*)d_in[1];
    const float* Wq    = (const float*)d_in[2];
    const float* Wk    = (const float*)d_in[3];
    const float* Wv    = (const float*)d_in[4];
    const float* Wo    = (const float*)d_in[5];
    const float* Wp    = (const float*)d_in[6];
    const float* bp    = (const float*)d_in[7];
    const float* W1    = (const float*)d_in[8];
    const float* b1    = (const float*)d_in[9];
    const float* W2    = (const float*)d_in[10];
    const float* b2    = (const float*)d_in[11];
    const float* g_att = (const float*)d_in[12];
    const float* b_att = (const float*)d_in[13];
    const float* g_ff  = (const float*)d_in[14];
    const float* b_ff  = (const float*)d_in[15];
    float* outp = (float*)d_out;

    cudaFuncSetAttribute(attn_kernel, cudaFuncAttributeMaxDynamicSharedMemorySize,
                         ATTN_SMEM_BYTES);

    qkv_kernel<<<dim3(32, 8, 3), 256>>>(seq, Wq, Wk, Wv);
    posbias_kernel<<<dim3(4, 512, 4), 128>>>(pos, Wp, bp);
    attn_kernel<<<dim3(32, 16), 256, ATTN_SMEM_BYTES>>>();
    proj_ln_kernel<<<128, 256>>>(seq, Wo, g_att, b_att);
    ffn_ln_kernel<<<512, 256>>>(W1, b1, W2, b2, g_ff, b_ff, outp);
}

// round 3
// speedup vs baseline: 1.4036x; 1.2407x over previous
#include <cuda_runtime.h>
#include <math.h>

// Problem constants
#define BN   4
#define SN   512
#define DN   64
#define HN   8
#define FFN  128
#define EPSV 1e-5f

typedef unsigned long long u64;
typedef unsigned int u32;

// ---------------------------------------------------------------------------
// Packed fp32x2 helpers (sm_100+): 2 IEEE fp32 FMAs per instruction.
// ---------------------------------------------------------------------------
__device__ __forceinline__ u64 pack2(float lo, float hi) {
    u64 r; asm("mov.b64 %0, {%1, %2};" : "=l"(r) : "f"(lo), "f"(hi)); return r;
}
__device__ __forceinline__ u64 dup2(float x) {
    u64 r; asm("mov.b64 %0, {%1, %1};" : "=l"(r) : "f"(x)); return r;
}
__device__ __forceinline__ void ffma2(u64& d, u64 a, u64 b) {
    asm("fma.rn.f32x2 %0, %1, %2, %0;" : "+l"(d) : "l"(a), "l"(b));
}
__device__ __forceinline__ float2 unpack2(u64 v) {
    float2 f; asm("mov.b64 {%0, %1}, %2;" : "=f"(f.x), "=f"(f.y) : "l"(v)); return f;
}

// ---------------------------------------------------------------------------
// tf32 MMA helpers (3xTF32 split for ~fp32 accuracy)
// ---------------------------------------------------------------------------
__device__ __forceinline__ u32 tf32_of(float x) {
    u32 r; asm("cvt.rna.tf32.f32 %0, %1;" : "=r"(r) : "f"(x)); return r;
}
__device__ __forceinline__ void split_tf32(float x, u32& hi, u32& lo) {
    hi = tf32_of(x);
    lo = tf32_of(x - __uint_as_float(hi));
}
__device__ __forceinline__ void mma8(float* d, const u32* a, const u32* b) {
    asm volatile(
        "mma.sync.aligned.m16n8k8.row.col.f32.tf32.tf32.f32 "
        "{%0,%1,%2,%3}, {%4,%5,%6,%7}, {%8,%9}, {%0,%1,%2,%3};"
        : "+f"(d[0]), "+f"(d[1]), "+f"(d[2]), "+f"(d[3])
        : "r"(a[0]), "r"(a[1]), "r"(a[2]), "r"(a[3]), "r"(b[0]), "r"(b[1]));
}

// ---------------------------------------------------------------------------
// Scratch (device globals; no allocation allowed)
// ---------------------------------------------------------------------------
__device__ float g_q[BN * HN * SN * DN];          // 4 MB   [b,h,s,d]
__device__ float g_k[BN * HN * SN * DN];          // 4 MB
__device__ float g_v[BN * HN * SN * DN];          // 4 MB
__device__ float g_p[(size_t)BN * HN * SN * SN];  // 33.5MB [b,h,i,j]
__device__ float g_heads[BN * SN * HN * DN];      // 4 MB   [b,s, h*64+d]
__device__ float g_x[BN * SN * DN];               // 0.5MB  post-LN1 activations

// ---------------------------------------------------------------------------
// Kernel 1: QKV projection (FFMA2 version, unchanged).
// ---------------------------------------------------------------------------
__global__ __launch_bounds__(256) void qkv_kernel(
    const float* __restrict__ seq, const float* __restrict__ Wq,
    const float* __restrict__ Wk, const float* __restrict__ Wv)
{
    __shared__ float sA[64 * 65];
    __shared__ float sB[64 * 66];
    const int m0   = blockIdx.x * 64;
    const int head = blockIdx.y;
    const float* __restrict__ W =
        (blockIdx.z == 0) ? Wq : (blockIdx.z == 1 ? Wk : Wv);
    float* outB = (blockIdx.z == 0) ? g_q : (blockIdx.z == 1 ? g_k : g_v);
    const int tid = threadIdx.x;

    for (int idx = tid; idx < 64 * 16; idx += 256) {
        int r = idx >> 4, c = (idx & 15) << 2;
        float4 a4 = *reinterpret_cast<const float4*>(seq + (size_t)(m0 + r) * 64 + c);
        sA[r * 65 + c] = a4.x; sA[r * 65 + c + 1] = a4.y;
        sA[r * 65 + c + 2] = a4.z; sA[r * 65 + c + 3] = a4.w;
        float4 b4 = *reinterpret_cast<const float4*>(W + (size_t)r * 512 + head * 64 + c);
        sB[r * 66 + c] = b4.x; sB[r * 66 + c + 1] = b4.y;
        sB[r * 66 + c + 2] = b4.z; sB[r * 66 + c + 3] = b4.w;
    }
    __syncthreads();

    const int ty = tid >> 4, tx = tid & 15;
    u64 acc[4][2] = {};
    #pragma unroll 16
    for (int k = 0; k < 64; k++) {
        u64 b0 = *reinterpret_cast<const u64*>(&sB[k * 66 + tx * 4]);
        u64 b1 = *reinterpret_cast<const u64*>(&sB[k * 66 + tx * 4 + 2]);
        #pragma unroll
        for (int i = 0; i < 4; i++) {
            u64 a = dup2(sA[(ty * 4 + i) * 65 + k]);
            ffma2(acc[i][0], a, b0);
            ffma2(acc[i][1], a, b1);
        }
    }

    const int bb = m0 >> 9;
    const int s0 = m0 & 511;
    #pragma unroll
    for (int i = 0; i < 4; i++) {
        float2 p0 = unpack2(acc[i][0]), p1 = unpack2(acc[i][1]);
        float4 o4 = make_float4(p0.x, p0.y, p1.x, p1.y);
        *reinterpret_cast<float4*>(
            outB + ((size_t)((bb * HN + head) * SN + s0 + ty * 4 + i)) * DN + tx * 4) = o4;
    }
}

// ---------------------------------------------------------------------------
// Kernel 2: positional bias (HBM-floor bound, unchanged).
// ---------------------------------------------------------------------------
__global__ __launch_bounds__(128) void posbias_kernel(
    const float* __restrict__ pos, const float* __restrict__ Wp,
    const float* __restrict__ bp)
{
    __shared__ float sP[128][65];
    __shared__ float sW[64][8];
    __shared__ float sbp[8];
    const int jt  = blockIdx.x;
    const int i   = blockIdx.y;
    const int b   = blockIdx.z;
    const int tid = threadIdx.x;

    for (int idx = tid; idx < 512; idx += 128) sW[idx >> 3][idx & 7] = Wp[idx];
    if (tid < 8) sbp[tid] = bp[tid];

    const float* src = pos + (((size_t)b * SN + i) * SN + jt * 128) * DN;
    #pragma unroll
    for (int it = 0; it < 16; it++) {
        int idx = tid + it * 128;
        int r = idx >> 4, c = (idx & 15) << 2;
        float4 v4 = *reinterpret_cast<const float4*>(src + (size_t)r * 64 + c);
        sP[r][c] = v4.x; sP[r][c + 1] = v4.y; sP[r][c + 2] = v4.z; sP[r][c + 3] = v4.w;
    }
    __syncthreads();

    u64 acc[4];
    #pragma unroll
    for (int hp = 0; hp < 4; hp++) acc[hp] = pack2(sbp[2 * hp], sbp[2 * hp + 1]);
    #pragma unroll 16
    for (int d = 0; d < 64; d++) {
        u64 x = dup2(sP[tid][d]);
        #pragma unroll
        for (int hp = 0; hp < 4; hp++) {
            u64 w = *reinterpret_cast<const u64*>(&sW[d][2 * hp]);
            ffma2(acc[hp], x, w);
        }
    }

    const int j = jt * 128 + tid;
    #pragma unroll
    for (int hp = 0; hp < 4; hp++) {
        float2 v = unpack2(acc[hp]);
        g_p[(((size_t)b * HN + 2 * hp) * SN + i) * SN + j]     = v.x;
        g_p[(((size_t)b * HN + 2 * hp + 1) * SN + i) * SN + j] = v.y;
    }
}

// ---------------------------------------------------------------------------
// Kernel 3: attention via tf32 tensor-core MMA (3xTF32 split ~ fp32 exact).
// One block per (b,h) x 32-row i-tile; 8 warps; warp w: m-half (w&1)*16,
// n-quarter (w>>1)*16. Scores kept in smem; exact softmax; 1/sum in epilogue.
// smem: sQ[32][68] | sKV[64][72] | sS[32][516] | sInv[32]  = 93.4 KB
// ---------------------------------------------------------------------------
#define AT_TI 32
#define QLD   68
#define KLD   68
#define VLD   72
#define SLD   516
#define ATTN_SMEM_FLOATS (AT_TI * QLD + 64 * VLD + AT_TI * SLD + AT_TI)
#define ATTN_SMEM_BYTES  (ATTN_SMEM_FLOATS * 4)

__global__ __launch_bounds__(256, 2) void attn_kernel()
{
    extern __shared__ float sm[];
    float* sQ   = sm;                     // [32][68]
    float* sKV  = sQ + AT_TI * QLD;       // [64][72] (K: stride 68 / V: stride 72)
    float* sS   = sKV + 64 * VLD;         // [32][516]
    float* sInv = sS + AT_TI * SLD;       // [32]

    const int bh  = blockIdx.x;           // b*8 + h
    const int i0  = blockIdx.y * AT_TI;
    const int tid = threadIdx.x;
    const int w    = tid >> 5, lane = tid & 31;
    const int mh   = (w & 1) * 16;        // m offset in tile
    const int nq   = (w >> 1) * 16;       // n-quarter offset
    const int lr   = lane >> 2, lc = lane & 3;

    // ---- load Q tile [32][64]
    const float* qsrc = g_q + ((size_t)bh * SN + i0) * DN;
    #pragma unroll
    for (int it = 0; it < 2; it++) {
        int id = tid + it * 256;
        int r = id >> 4, c = (id & 15) << 2;
        float4 v = *reinterpret_cast<const float4*>(qsrc + (size_t)r * 64 + c);
        sQ[r * QLD + c] = v.x; sQ[r * QLD + c + 1] = v.y;
        sQ[r * QLD + c + 2] = v.z; sQ[r * QLD + c + 3] = v.w;
    }
    __syncthreads();

    // ---- preload Q fragments (hi/lo), 8 k-steps, reused across all chunks
    u32 qh[8][4], ql[8][4];
    #pragma unroll
    for (int k8 = 0; k8 < 8; k8++) {
        float a0 = sQ[(mh + lr) * QLD + k8 * 8 + lc];
        float a1 = sQ[(mh + lr + 8) * QLD + k8 * 8 + lc];
        float a2 = sQ[(mh + lr) * QLD + k8 * 8 + lc + 4];
        float a3 = sQ[(mh + lr + 8) * QLD + k8 * 8 + lc + 4];
        split_tf32(a0, qh[k8][0], ql[k8][0]);
        split_tf32(a1, qh[k8][1], ql[k8][1]);
        split_tf32(a2, qh[k8][2], ql[k8][2]);
        split_tf32(a3, qh[k8][3], ql[k8][3]);
    }
    const float* pbase = g_p + ((size_t)bh * SN + i0) * SN;

    // ---- Phase 1: S = QK^T * 0.125 + P
    for (int jt = 0; jt < 8; jt++) {
        __syncthreads();
        const float* ksrc = g_k + ((size_t)bh * SN + jt * 64) * DN;
        #pragma unroll
        for (int it = 0; it < 4; it++) {
            int id = tid + it * 256;
            int r = id >> 4, c = (id & 15) << 2;
            float4 v = *reinterpret_cast<const float4*>(ksrc + (size_t)r * 64 + c);
            sKV[r * KLD + c] = v.x; sKV[r * KLD + c + 1] = v.y;
            sKV[r * KLD + c + 2] = v.z; sKV[r * KLD + c + 3] = v.w;
        }
        __syncthreads();

        float D[2][4] = {};
        #pragma unroll
        for (int k8 = 0; k8 < 8; k8++) {
            #pragma unroll
            for (int nt = 0; nt < 2; nt++) {
                float b0f = sKV[(nq + nt * 8 + lr) * KLD + k8 * 8 + lc];
                float b1f = sKV[(nq + nt * 8 + lr) * KLD + k8 * 8 + lc + 4];
                u32 bh0, bl0, bh1, bl1;
                split_tf32(b0f, bh0, bl0);
                split_tf32(b1f, bh1, bl1);
                u32 Bh[2] = {bh0, bh1}, Bl[2] = {bl0, bl1};
                mma8(D[nt], qh[k8], Bh);
                mma8(D[nt], ql[k8], Bh);
                mma8(D[nt], qh[k8], Bl);
            }
        }
        #pragma unroll
        for (int nt = 0; nt < 2; nt++) {
            int col = jt * 64 + nq + nt * 8 + 2 * lc;
            float2 p0 = *reinterpret_cast<const float2*>(pbase + (size_t)(mh + lr) * SN + col);
            float2 p1 = *reinterpret_cast<const float2*>(pbase + (size_t)(mh + lr + 8) * SN + col);
            *reinterpret_cast<float2*>(&sS[(mh + lr) * SLD + col]) =
                make_float2(D[nt][0] * 0.125f + p0.x, D[nt][1] * 0.125f + p0.y);
            *reinterpret_cast<float2*>(&sS[(mh + lr + 8) * SLD + col]) =
                make_float2(D[nt][2] * 0.125f + p1.x, D[nt][3] * 0.125f + p1.y);
        }
    }
    __syncthreads();

    // ---- Phase 2: softmax (unnormalized; 1/sum folded into epilogue)
    #pragma unroll
    for (int rr = 0; rr < 4; rr++) {
        int r = w * 4 + rr;
        float* row = sS + r * SLD;
        float mx = -1e30f;
        #pragma unroll
        for (int c = 0; c < 16; c++) mx = fmaxf(mx, row[lane + c * 32]);
        #pragma unroll
        for (int off = 16; off > 0; off >>= 1)
            mx = fmaxf(mx, __shfl_xor_sync(0xffffffffu, mx, off));
        float sum = 0.f;
        #pragma unroll
        for (int c = 0; c < 16; c++) {
            float e = __expf(row[lane + c * 32] - mx);
            row[lane + c * 32] = e;
            sum += e;
        }
        #pragma unroll
        for (int off = 16; off > 0; off >>= 1)
            sum += __shfl_xor_sync(0xffffffffu, sum, off);
        if (lane == 0) sInv[r] = 1.f / sum;
    }
    __syncthreads();

    // ---- Phase 3: O = A @ V
    float O[2][4] = {};
    for (int jt = 0; jt < 8; jt++) {
        __syncthreads();
        const float* vsrc = g_v + ((size_t)bh * SN + jt * 64) * DN;
        #pragma unroll
        for (int it = 0; it < 4; it++) {
            int id = tid + it * 256;
            int r = id >> 4, c = (id & 15) << 2;
            float4 v = *reinterpret_cast<const float4*>(vsrc + (size_t)r * 64 + c);
            sKV[r * VLD + c] = v.x; sKV[r * VLD + c + 1] = v.y;
            sKV[r * VLD + c + 2] = v.z; sKV[r * VLD + c + 3] = v.w;
        }
        __syncthreads();

        #pragma unroll
        for (int k8 = 0; k8 < 8; k8++) {
            int kk = jt * 64 + k8 * 8;
            float a0 = sS[(mh + lr) * SLD + kk + lc];
            float a1 = sS[(mh + lr + 8) * SLD + kk + lc];
            float a2 = sS[(mh + lr) * SLD + kk + lc + 4];
            float a3 = sS[(mh + lr + 8) * SLD + kk + lc + 4];
            u32 Ah[4], Al[4];
            split_tf32(a0, Ah[0], Al[0]);
            split_tf32(a1, Ah[1], Al[1]);
            split_tf32(a2, Ah[2], Al[2]);
            split_tf32(a3, Ah[3], Al[3]);
            #pragma unroll
            for (int nt = 0; nt < 2; nt++) {
                float b0f = sKV[(k8 * 8 + lc) * VLD + nq + nt * 8 + lr];
                float b1f = sKV[(k8 * 8 + lc + 4) * VLD + nq + nt * 8 + lr];
                u32 bh0, bl0, bh1, bl1;
                split_tf32(b0f, bh0, bl0);
                split_tf32(b1f, bh1, bl1);
                u32 Bh[2] = {bh0, bh1}, Bl[2] = {bl0, bl1};
                mma8(O[nt], Ah, Bh);
                mma8(O[nt], Al, Bh);
                mma8(O[nt], Ah, Bl);
            }
        }
    }

    // ---- epilogue: scale by 1/sum, store to g_heads
    const int b_ = bh >> 3, h_ = bh & 7;
    float inv0 = sInv[mh + lr], inv1 = sInv[mh + lr + 8];
    #pragma unroll
    for (int nt = 0; nt < 2; nt++) {
        int col = h_ * 64 + nq + nt * 8 + 2 * lc;
        float* o0 = g_heads + ((size_t)(b_ * SN + i0 + mh + lr)) * (HN * DN) + col;
        float* o1 = g_heads + ((size_t)(b_ * SN + i0 + mh + lr + 8)) * (HN * DN) + col;
        *reinterpret_cast<float2*>(o0) = make_float2(O[nt][0] * inv0, O[nt][1] * inv0);
        *reinterpret_cast<float2*>(o1) = make_float2(O[nt][2] * inv1, O[nt][3] * inv1);
    }
}

// ---------------------------------------------------------------------------
// Kernel 4a: o = heads @ Wo ; x = LN(seq + o) -> g_x.
// One row per warp, streaming: no inter-chunk syncs, Wo L1-resident.
// grid 256 x 8 warps = 2048 rows.
// ---------------------------------------------------------------------------
__global__ __launch_bounds__(256) void proj_ln_kernel(
    const float* __restrict__ seq, const float* __restrict__ Wo,
    const float* __restrict__ gam, const float* __restrict__ bet)
{
    __shared__ float sH[8][512];
    const int tid = threadIdx.x, w = tid >> 5, lane = tid & 31;
    const size_t m0 = (size_t)blockIdx.x * 8;

    #pragma unroll
    for (int it = 0; it < 4; it++) {
        int id = tid + it * 256;
        int r = id >> 7, c = (id & 127) << 2;
        *reinterpret_cast<float4*>(&sH[r][c]) =
            *reinterpret_cast<const float4*>(g_heads + (m0 + r) * 512 + c);
    }
    __syncthreads();

    const size_t m = m0 + w;
    u64 acc = 0;
    #pragma unroll 8
    for (int k = 0; k < 512; k++) {
        u64 wv = *reinterpret_cast<const u64*>(Wo + (size_t)k * 64 + 2 * lane);
        ffma2(acc, dup2(sH[w][k]), wv);
    }
    float2 a = unpack2(acc);
    float2 sv = *reinterpret_cast<const float2*>(seq + m * 64 + 2 * lane);
    float x0 = a.x + sv.x, x1 = a.y + sv.y;

    float s = x0 + x1, ss = x0 * x0 + x1 * x1;
    #pragma unroll
    for (int off = 16; off > 0; off >>= 1) {
        s  += __shfl_xor_sync(0xffffffffu, s, off);
        ss += __shfl_xor_sync(0xffffffffu, ss, off);
    }
    float mu  = s * (1.f / 64.f);
    float var = ss * (1.f / 64.f) - mu * mu;
    float rs  = rsqrtf(var + EPSV);
    g_x[m * 64 + 2 * lane]     = (x0 - mu) * rs * gam[2 * lane]     + bet[2 * lane];
    g_x[m * 64 + 2 * lane + 1] = (x1 - mu) * rs * gam[2 * lane + 1] + bet[2 * lane + 1];
}

// ---------------------------------------------------------------------------
// Kernel 4b: y = relu(x@W1+b1)@W2+b2 ; out = LN(x+y). (unchanged)
// ---------------------------------------------------------------------------
__global__ __launch_bounds__(256) void ffn_ln_kernel(
    const float* __restrict__ W1, const float* __restrict__ b1,
    const float* __restrict__ W2, const float* __restrict__ b2,
    const float* __restrict__ gam, const float* __restrict__ bet,
    float* __restrict__ out)
{
    __shared__ float sX[4][64];
    __shared__ float sY[4][128];
    __shared__ float sPp[4][64];
    __shared__ float sZ[4][64];
    const int tid  = threadIdx.x;
    const int r4   = tid >> 6;
    const int t    = tid & 63;
    const size_t row = (size_t)blockIdx.x * 4 + r4;

    sX[r4][t] = g_x[row * 64 + t];
    __syncthreads();

    u64 a1 = *reinterpret_cast<const u64*>(b1 + 2 * t);
    #pragma unroll 16
    for (int d = 0; d < 64; d++) {
        u64 w = *reinterpret_cast<const u64*>(W1 + (size_t)d * 128 + 2 * t);
        ffma2(a1, dup2(sX[r4][d]), w);
    }
    {
        float2 y = unpack2(a1);
        sY[r4][2 * t]     = fmaxf(y.x, 0.f);
        sY[r4][2 * t + 1] = fmaxf(y.y, 0.f);
    }
    __syncthreads();

    const int u = t & 31, g = t >> 5;
    u64 a2 = 0;
    #pragma unroll 16
    for (int f = 0; f < 64; f++) {
        u64 w = *reinterpret_cast<const u64*>(W2 + (size_t)(g * 64 + f) * 64 + 2 * u);
        ffma2(a2, dup2(sY[r4][g * 64 + f]), w);
    }
    float2 p = unpack2(a2);
    if (g == 1) { sPp[r4][2 * u] = p.x; sPp[r4][2 * u + 1] = p.y; }
    __syncthreads();
    if (g == 0) {
        sZ[r4][2 * u]     = p.x + sPp[r4][2 * u]     + b2[2 * u]     + sX[r4][2 * u];
        sZ[r4][2 * u + 1] = p.y + sPp[r4][2 * u + 1] + b2[2 * u + 1] + sX[r4][2 * u + 1];
    }
    __syncthreads();

    if (g == 0) {
        float z0 = sZ[r4][u], z1 = sZ[r4][u + 32];
        float s = z0 + z1, ss = z0 * z0 + z1 * z1;
        #pragma unroll
        for (int off = 16; off > 0; off >>= 1) {
            s  += __shfl_xor_sync(0xffffffffu, s, off);
            ss += __shfl_xor_sync(0xffffffffu, ss, off);
        }
        float mu  = s * (1.f / 64.f);
        float var = ss * (1.f / 64.f) - mu * mu;
        float rs  = rsqrtf(var + EPSV);
        out[row * 64 + u]      = (z0 - mu) * rs * gam[u] + bet[u];
        out[row * 64 + u + 32] = (z1 - mu) * rs * gam[u + 32] + bet[u + 32];
    }
}

// ---------------------------------------------------------------------------
// Launch
// ---------------------------------------------------------------------------
extern "C" void kernel_launch(void* const* d_in, const int* in_sizes, int n_in,
                              void* d_out, int out_size)
{
    const float* seq   = (const float*)d_in[0];
    const float* pos   = (const float*)d_in[1];
    const float* Wq    = (const float*)d_in[2];
    const float* Wk    = (const float*)d_in[3];
    const float* Wv    = (const float*)d_in[4];
    const float* Wo    = (const float*)d_in[5];
    const float* Wp    = (const float*)d_in[6];
    const float* bp    = (const float*)d_in[7];
    const float* W1    = (const float*)d_in[8];
    const float* b1    = (const float*)d_in[9];
    const float* W2    = (const float*)d_in[10];
    const float* b2    = (const float*)d_in[11];
    const float* g_att = (const float*)d_in[12];
    const float* b_att = (const float*)d_in[13];
    const float* g_ff  = (const float*)d_in[14];
    const float* b_ff  = (const float*)d_in[15];
    float* outp = (float*)d_out;

    cudaFuncSetAttribute(attn_kernel, cudaFuncAttributeMaxDynamicSharedMemorySize,
                         ATTN_SMEM_BYTES);

    qkv_kernel<<<dim3(32, 8, 3), 256>>>(seq, Wq, Wk, Wv);
    posbias_kernel<<<dim3(4, 512, 4), 128>>>(pos, Wp, bp);
    attn_kernel<<<dim3(32, 16), 256, ATTN_SMEM_BYTES>>>();
    proj_ln_kernel<<<256, 256>>>(seq, Wo, g_att, b_att);
    ffn_ln_kernel<<<512, 256>>>(W1, b1, W2, b2, g_ff, b_ff, outp);
}

// round 6
// speedup vs baseline: 1.6260x; 1.1584x over previous
#include <cuda_runtime.h>
#include <math.h>

// Problem constants
#define BN   4
#define SN   512
#define DN   64
#define HN   8
#define FFN  128
#define EPSV 1e-5f

typedef unsigned long long u64;
typedef unsigned int u32;

// ---------------------------------------------------------------------------
// Packed fp32x2 helpers (sm_100+)
// ---------------------------------------------------------------------------
__device__ __forceinline__ u64 pack2(float lo, float hi) {
    u64 r; asm("mov.b64 %0, {%1, %2};" : "=l"(r) : "f"(lo), "f"(hi)); return r;
}
__device__ __forceinline__ u64 dup2(float x) {
    u64 r; asm("mov.b64 %0, {%1, %1};" : "=l"(r) : "f"(x)); return r;
}
__device__ __forceinline__ void ffma2(u64& d, u64 a, u64 b) {
    asm("fma.rn.f32x2 %0, %1, %2, %0;" : "+l"(d) : "l"(a), "l"(b));
}
__device__ __forceinline__ u64 addp2(u64 a, u64 b) {
    u64 r; asm("add.rn.f32x2 %0, %1, %2;" : "=l"(r) : "l"(a), "l"(b)); return r;
}
__device__ __forceinline__ float2 unpack2(u64 v) {
    float2 f; asm("mov.b64 {%0, %1}, %2;" : "=f"(f.x), "=f"(f.y) : "l"(v)); return f;
}

// cp.async helpers
__device__ __forceinline__ void cp_async16(u32 smem_addr, const void* gptr) {
    asm volatile("cp.async.cg.shared.global [%0], [%1], 16;"
                 :: "r"(smem_addr), "l"(gptr));
}
__device__ __forceinline__ void cp_commit() {
    asm volatile("cp.async.commit_group;");
}
template<int N> __device__ __forceinline__ void cp_wait() {
    asm volatile("cp.async.wait_group %0;" :: "n"(N));
}

// ---------------------------------------------------------------------------
// tf32 MMA helpers (3xTF32 split)
// ---------------------------------------------------------------------------
__device__ __forceinline__ u32 tf32_of(float x) {
    u32 r; asm("cvt.rna.tf32.f32 %0, %1;" : "=r"(r) : "f"(x)); return r;
}
__device__ __forceinline__ void split_tf32(float x, u32& hi, u32& lo) {
    hi = tf32_of(x);
    lo = tf32_of(x - __uint_as_float(hi));
}
__device__ __forceinline__ void mma8(float* d, const u32* a, const u32* b) {
    asm volatile(
        "mma.sync.aligned.m16n8k8.row.col.f32.tf32.tf32.f32 "
        "{%0,%1,%2,%3}, {%4,%5,%6,%7}, {%8,%9}, {%0,%1,%2,%3};"
        : "+f"(d[0]), "+f"(d[1]), "+f"(d[2]), "+f"(d[3])
        : "r"(a[0]), "r"(a[1]), "r"(a[2]), "r"(a[3]), "r"(b[0]), "r"(b[1]));
}

// ---------------------------------------------------------------------------
// Scratch
// ---------------------------------------------------------------------------
__device__ float g_q[BN * HN * SN * DN];
__device__ float g_k[BN * HN * SN * DN];
__device__ float g_v[BN * HN * SN * DN];
__device__ float g_p[(size_t)BN * HN * SN * SN];
__device__ float g_heads[BN * SN * HN * DN];
__device__ float g_x[BN * SN * DN];

// ---------------------------------------------------------------------------
// Kernel 1: QKV projection (unchanged)
// ---------------------------------------------------------------------------
__global__ __launch_bounds__(256) void qkv_kernel(
    const float* __restrict__ seq, const float* __restrict__ Wq,
    const float* __restrict__ Wk, const float* __restrict__ Wv)
{
    __shared__ float sA[64 * 65];
    __shared__ float sB[64 * 66];
    const int m0   = blockIdx.x * 64;
    const int head = blockIdx.y;
    const float* __restrict__ W =
        (blockIdx.z == 0) ? Wq : (blockIdx.z == 1 ? Wk : Wv);
    float* outB = (blockIdx.z == 0) ? g_q : (blockIdx.z == 1 ? g_k : g_v);
    const int tid = threadIdx.x;

    for (int idx = tid; idx < 64 * 16; idx += 256) {
        int r = idx >> 4, c = (idx & 15) << 2;
        float4 a4 = *reinterpret_cast<const float4*>(seq + (size_t)(m0 + r) * 64 + c);
        sA[r * 65 + c] = a4.x; sA[r * 65 + c + 1] = a4.y;
        sA[r * 65 + c + 2] = a4.z; sA[r * 65 + c + 3] = a4.w;
        float4 b4 = *reinterpret_cast<const float4*>(W + (size_t)r * 512 + head * 64 + c);
        sB[r * 66 + c] = b4.x; sB[r * 66 + c + 1] = b4.y;
        sB[r * 66 + c + 2] = b4.z; sB[r * 66 + c + 3] = b4.w;
    }
    __syncthreads();

    const int ty = tid >> 4, tx = tid & 15;
    u64 acc[4][2] = {};
    #pragma unroll 16
    for (int k = 0; k < 64; k++) {
        u64 b0 = *reinterpret_cast<const u64*>(&sB[k * 66 + tx * 4]);
        u64 b1 = *reinterpret_cast<const u64*>(&sB[k * 66 + tx * 4 + 2]);
        #pragma unroll
        for (int i = 0; i < 4; i++) {
            u64 a = dup2(sA[(ty * 4 + i) * 65 + k]);
            ffma2(acc[i][0], a, b0);
            ffma2(acc[i][1], a, b1);
        }
    }

    const int bb = m0 >> 9;
    const int s0 = m0 & 511;
    #pragma unroll
    for (int i = 0; i < 4; i++) {
        float2 p0 = unpack2(acc[i][0]), p1 = unpack2(acc[i][1]);
        float4 o4 = make_float4(p0.x, p0.y, p1.x, p1.y);
        *reinterpret_cast<float4*>(
            outB + ((size_t)((bb * HN + head) * SN + s0 + ty * 4 + i)) * DN + tx * 4) = o4;
    }
}

// ---------------------------------------------------------------------------
// Kernel 2: positional bias (unchanged; HBM-floor)
// ---------------------------------------------------------------------------
__global__ __launch_bounds__(128) void posbias_kernel(
    const float* __restrict__ pos, const float* __restrict__ Wp,
    const float* __restrict__ bp)
{
    __shared__ float sP[128][65];
    __shared__ float sW[64][8];
    __shared__ float sbp[8];
    const int jt  = blockIdx.x;
    const int i   = blockIdx.y;
    const int b   = blockIdx.z;
    const int tid = threadIdx.x;

    for (int idx = tid; idx < 512; idx += 128) sW[idx >> 3][idx & 7] = Wp[idx];
    if (tid < 8) sbp[tid] = bp[tid];

    const float* src = pos + (((size_t)b * SN + i) * SN + jt * 128) * DN;
    #pragma unroll
    for (int it = 0; it < 16; it++) {
        int idx = tid + it * 128;
        int r = idx >> 4, c = (idx & 15) << 2;
        float4 v4 = *reinterpret_cast<const float4*>(src + (size_t)r * 64 + c);
        sP[r][c] = v4.x; sP[r][c + 1] = v4.y; sP[r][c + 2] = v4.z; sP[r][c + 3] = v4.w;
    }
    __syncthreads();

    u64 acc[4];
    #pragma unroll
    for (int hp = 0; hp < 4; hp++) acc[hp] = pack2(sbp[2 * hp], sbp[2 * hp + 1]);
    #pragma unroll 16
    for (int d = 0; d < 64; d++) {
        u64 x = dup2(sP[tid][d]);
        #pragma unroll
        for (int hp = 0; hp < 4; hp++) {
            u64 w = *reinterpret_cast<const u64*>(&sW[d][2 * hp]);
            ffma2(acc[hp], x, w);
        }
    }

    const int j = jt * 128 + tid;
    #pragma unroll
    for (int hp = 0; hp < 4; hp++) {
        float2 v = unpack2(acc[hp]);
        g_p[(((size_t)b * HN + 2 * hp) * SN + i) * SN + j]     = v.x;
        g_p[(((size_t)b * HN + 2 * hp + 1) * SN + i) * SN + j] = v.y;
    }
}

// ---------------------------------------------------------------------------
// Kernel 3: attention via tf32 MMA (unchanged from R3)
// ---------------------------------------------------------------------------
#define AT_TI 32
#define QLD   68
#define KLD   68
#define VLD   72
#define SLD   516
#define ATTN_SMEM_FLOATS (AT_TI * QLD + 64 * VLD + AT_TI * SLD + AT_TI)
#define ATTN_SMEM_BYTES  (ATTN_SMEM_FLOATS * 4)

__global__ __launch_bounds__(256, 2) void attn_kernel()
{
    extern __shared__ float sm[];
    float* sQ   = sm;
    float* sKV  = sQ + AT_TI * QLD;
    float* sS   = sKV + 64 * VLD;
    float* sInv = sS + AT_TI * SLD;

    const int bh  = blockIdx.x;
    const int i0  = blockIdx.y * AT_TI;
    const int tid = threadIdx.x;
    const int w    = tid >> 5, lane = tid & 31;
    const int mh   = (w & 1) * 16;
    const int nq   = (w >> 1) * 16;
    const int lr   = lane >> 2, lc = lane & 3;

    const float* qsrc = g_q + ((size_t)bh * SN + i0) * DN;
    #pragma unroll
    for (int it = 0; it < 2; it++) {
        int id = tid + it * 256;
        int r = id >> 4, c = (id & 15) << 2;
        float4 v = *reinterpret_cast<const float4*>(qsrc + (size_t)r * 64 + c);
        sQ[r * QLD + c] = v.x; sQ[r * QLD + c + 1] = v.y;
        sQ[r * QLD + c + 2] = v.z; sQ[r * QLD + c + 3] = v.w;
    }
    __syncthreads();

    u32 qh[8][4], ql[8][4];
    #pragma unroll
    for (int k8 = 0; k8 < 8; k8++) {
        float a0 = sQ[(mh + lr) * QLD + k8 * 8 + lc];
        float a1 = sQ[(mh + lr + 8) * QLD + k8 * 8 + lc];
        float a2 = sQ[(mh + lr) * QLD + k8 * 8 + lc + 4];
        float a3 = sQ[(mh + lr + 8) * QLD + k8 * 8 + lc + 4];
        split_tf32(a0, qh[k8][0], ql[k8][0]);
        split_tf32(a1, qh[k8][1], ql[k8][1]);
        split_tf32(a2, qh[k8][2], ql[k8][2]);
        split_tf32(a3, qh[k8][3], ql[k8][3]);
    }
    const float* pbase = g_p + ((size_t)bh * SN + i0) * SN;

    for (int jt = 0; jt < 8; jt++) {
        __syncthreads();
        const float* ksrc = g_k + ((size_t)bh * SN + jt * 64) * DN;
        #pragma unroll
        for (int it = 0; it < 4; it++) {
            int id = tid + it * 256;
            int r = id >> 4, c = (id & 15) << 2;
            float4 v = *reinterpret_cast<const float4*>(ksrc + (size_t)r * 64 + c);
            sKV[r * KLD + c] = v.x; sKV[r * KLD + c + 1] = v.y;
            sKV[r * KLD + c + 2] = v.z; sKV[r * KLD + c + 3] = v.w;
        }
        __syncthreads();

        float D[2][4] = {};
        #pragma unroll
        for (int k8 = 0; k8 < 8; k8++) {
            #pragma unroll
            for (int nt = 0; nt < 2; nt++) {
                float b0f = sKV[(nq + nt * 8 + lr) * KLD + k8 * 8 + lc];
                float b1f = sKV[(nq + nt * 8 + lr) * KLD + k8 * 8 + lc + 4];
                u32 bh0, bl0, bh1, bl1;
                split_tf32(b0f, bh0, bl0);
                split_tf32(b1f, bh1, bl1);
                u32 Bh[2] = {bh0, bh1}, Bl[2] = {bl0, bl1};
                mma8(D[nt], qh[k8], Bh);
                mma8(D[nt], ql[k8], Bh);
                mma8(D[nt], qh[k8], Bl);
            }
        }
        #pragma unroll
        for (int nt = 0; nt < 2; nt++) {
            int col = jt * 64 + nq + nt * 8 + 2 * lc;
            float2 p0 = *reinterpret_cast<const float2*>(pbase + (size_t)(mh + lr) * SN + col);
            float2 p1 = *reinterpret_cast<const float2*>(pbase + (size_t)(mh + lr + 8) * SN + col);
            *reinterpret_cast<float2*>(&sS[(mh + lr) * SLD + col]) =
                make_float2(D[nt][0] * 0.125f + p0.x, D[nt][1] * 0.125f + p0.y);
            *reinterpret_cast<float2*>(&sS[(mh + lr + 8) * SLD + col]) =
                make_float2(D[nt][2] * 0.125f + p1.x, D[nt][3] * 0.125f + p1.y);
        }
    }
    __syncthreads();

    #pragma unroll
    for (int rr = 0; rr < 4; rr++) {
        int r = w * 4 + rr;
        float* row = sS + r * SLD;
        float mx = -1e30f;
        #pragma unroll
        for (int c = 0; c < 16; c++) mx = fmaxf(mx, row[lane + c * 32]);
        #pragma unroll
        for (int off = 16; off > 0; off >>= 1)
            mx = fmaxf(mx, __shfl_xor_sync(0xffffffffu, mx, off));
        float sum = 0.f;
        #pragma unroll
        for (int c = 0; c < 16; c++) {
            float e = __expf(row[lane + c * 32] - mx);
            row[lane + c * 32] = e;
            sum += e;
        }
        #pragma unroll
        for (int off = 16; off > 0; off >>= 1)
            sum += __shfl_xor_sync(0xffffffffu, sum, off);
        if (lane == 0) sInv[r] = 1.f / sum;
    }
    __syncthreads();

    float O[2][4] = {};
    for (int jt = 0; jt < 8; jt++) {
        __syncthreads();
        const float* vsrc = g_v + ((size_t)bh * SN + jt * 64) * DN;
        #pragma unroll
        for (int it = 0; it < 4; it++) {
            int id = tid + it * 256;
            int r = id >> 4, c = (id & 15) << 2;
            float4 v = *reinterpret_cast<const float4*>(vsrc + (size_t)r * 64 + c);
            sKV[r * VLD + c] = v.x; sKV[r * VLD + c + 1] = v.y;
            sKV[r * VLD + c + 2] = v.z; sKV[r * VLD + c + 3] = v.w;
        }
        __syncthreads();

        #pragma unroll
        for (int k8 = 0; k8 < 8; k8++) {
            int kk = jt * 64 + k8 * 8;
            float a0 = sS[(mh + lr) * SLD + kk + lc];
            float a1 = sS[(mh + lr + 8) * SLD + kk + lc];
            float a2 = sS[(mh + lr) * SLD + kk + lc + 4];
            float a3 = sS[(mh + lr + 8) * SLD + kk + lc + 4];
            u32 Ah[4], Al[4];
            split_tf32(a0, Ah[0], Al[0]);
            split_tf32(a1, Ah[1], Al[1]);
            split_tf32(a2, Ah[2], Al[2]);
            split_tf32(a3, Ah[3], Al[3]);
            #pragma unroll
            for (int nt = 0; nt < 2; nt++) {
                float b0f = sKV[(k8 * 8 + lc) * VLD + nq + nt * 8 + lr];
                float b1f = sKV[(k8 * 8 + lc + 4) * VLD + nq + nt * 8 + lr];
                u32 bh0, bl0, bh1, bl1;
                split_tf32(b0f, bh0, bl0);
                split_tf32(b1f, bh1, bl1);
                u32 Bh[2] = {bh0, bh1}, Bl[2] = {bl0, bl1};
                mma8(O[nt], Ah, Bh);
                mma8(O[nt], Al, Bh);
                mma8(O[nt], Ah, Bl);
            }
        }
    }

    const int b_ = bh >> 3, h_ = bh & 7;
    float inv0 = sInv[mh + lr], inv1 = sInv[mh + lr + 8];
    #pragma unroll
    for (int nt = 0; nt < 2; nt++) {
        int col = h_ * 64 + nq + nt * 8 + 2 * lc;
        float* o0 = g_heads + ((size_t)(b_ * SN + i0 + mh + lr)) * (HN * DN) + col;
        float* o1 = g_heads + ((size_t)(b_ * SN + i0 + mh + lr + 8)) * (HN * DN) + col;
        *reinterpret_cast<float2*>(o0) = make_float2(O[nt][0] * inv0, O[nt][1] * inv0);
        *reinterpret_cast<float2*>(o1) = make_float2(O[nt][2] * inv1, O[nt][3] * inv1);
    }
}

// ---------------------------------------------------------------------------
// Kernel 4a v3: o = heads @ Wo ; x = LN(seq + o) -> g_x.
// grid 128 x 512 thr. 16 rows/block; warp w owns row w. Wo double-buffered
// via cp.async. B-tile stride 68 floats (272 B, 16B-aligned rows for
// cp.async16 -- stride 66 caused R5's misaligned-address fault).
// ---------------------------------------------------------------------------
#define PROJ_BLD 68
#define PROJ_SH_FLOATS (16 * 516)
#define PROJ_SB_FLOATS (64 * PROJ_BLD)
#define PROJ_SMEM_BYTES ((PROJ_SH_FLOATS + 2 * PROJ_SB_FLOATS) * 4)

__global__ __launch_bounds__(512) void proj_ln_kernel(
    const float* __restrict__ seq, const float* __restrict__ Wo,
    const float* __restrict__ gam, const float* __restrict__ bet)
{
    extern __shared__ float psm[];
    float* sH  = psm;                              // [16][516]
    float* sB0 = psm + PROJ_SH_FLOATS;             // [64][68] buf 0
    float* sB1 = sB0 + PROJ_SB_FLOATS;             // [64][68] buf 1
    const int tid = threadIdx.x, w = tid >> 5, lane = tid & 31;
    const size_t m0 = (size_t)blockIdx.x * 16;

    // H tile: 16 x 512 (4 float4 per thread)
    #pragma unroll
    for (int it = 0; it < 4; it++) {
        int id = tid + it * 512;
        int r = id >> 7, c = (id & 127) << 2;
        float4 v = *reinterpret_cast<const float4*>(g_heads + (m0 + r) * 512 + c);
        sH[r * 516 + c] = v.x; sH[r * 516 + c + 1] = v.y;
        sH[r * 516 + c + 2] = v.z; sH[r * 516 + c + 3] = v.w;
    }

    // prefetch Wo chunk 0
    {
        #pragma unroll
        for (int it = 0; it < 2; it++) {
            int id = tid + it * 512;
            int r = id >> 4, c = (id & 15) << 2;
            cp_async16((u32)__cvta_generic_to_shared(&sB0[r * PROJ_BLD + c]),
                       Wo + (size_t)r * 64 + c);
        }
        cp_commit();
    }

    u64 acc[4] = {};
    for (int kc = 0; kc < 8; kc++) {
        float* cur = (kc & 1) ? sB1 : sB0;
        float* nxt = (kc & 1) ? sB0 : sB1;
        if (kc < 7) {
            #pragma unroll
            for (int it = 0; it < 2; it++) {
                int id = tid + it * 512;
                int r = id >> 4, c = (id & 15) << 2;
                cp_async16((u32)__cvta_generic_to_shared(&nxt[r * PROJ_BLD + c]),
                           Wo + (size_t)((kc + 1) * 64 + r) * 64 + c);
            }
            cp_commit();
            cp_wait<1>();
        } else {
            cp_wait<0>();
        }
        __syncthreads();

        const float* Hrow = &sH[w * 516 + kc * 64];
        #pragma unroll
        for (int k4 = 0; k4 < 16; k4++) {
            #pragma unroll
            for (int j = 0; j < 4; j++) {
                u64 bv = *reinterpret_cast<const u64*>(
                    &cur[(k4 * 4 + j) * PROJ_BLD + 2 * lane]);
                ffma2(acc[j], dup2(Hrow[k4 * 4 + j]), bv);
            }
        }
        __syncthreads();
    }

    u64 at = addp2(addp2(acc[0], acc[1]), addp2(acc[2], acc[3]));
    float2 a = unpack2(at);
    const size_t m = m0 + w;
    float2 sv = *reinterpret_cast<const float2*>(seq + m * 64 + 2 * lane);
    float x0 = a.x + sv.x, x1 = a.y + sv.y;

    float s = x0 + x1, ss = x0 * x0 + x1 * x1;
    #pragma unroll
    for (int off = 16; off > 0; off >>= 1) {
        s  += __shfl_xor_sync(0xffffffffu, s, off);
        ss += __shfl_xor_sync(0xffffffffu, ss, off);
    }
    float mu  = s * (1.f / 64.f);
    float var = ss * (1.f / 64.f) - mu * mu;
    float rs  = rsqrtf(var + EPSV);
    g_x[m * 64 + 2 * lane]     = (x0 - mu) * rs * gam[2 * lane]     + bet[2 * lane];
    g_x[m * 64 + 2 * lane + 1] = (x1 - mu) * rs * gam[2 * lane + 1] + bet[2 * lane + 1];
}

// ---------------------------------------------------------------------------
// Kernel 4b: FFN + LN2. Chains split into 2 independent accumulators.
// ---------------------------------------------------------------------------
__global__ __launch_bounds__(256) void ffn_ln_kernel(
    const float* __restrict__ W1, const float* __restrict__ b1,
    const float* __restrict__ W2, const float* __restrict__ b2,
    const float* __restrict__ gam, const float* __restrict__ bet,
    float* __restrict__ out)
{
    __shared__ float sX[4][64];
    __shared__ float sY[4][128];
    __shared__ float sPp[4][64];
    __shared__ float sZ[4][64];
    const int tid  = threadIdx.x;
    const int r4   = tid >> 6;
    const int t    = tid & 63;
    const size_t row = (size_t)blockIdx.x * 4 + r4;

    sX[r4][t] = g_x[row * 64 + t];
    __syncthreads();

    u64 a1a = *reinterpret_cast<const u64*>(b1 + 2 * t), a1b = 0;
    #pragma unroll 16
    for (int d = 0; d < 64; d += 2) {
        u64 w0 = *reinterpret_cast<const u64*>(W1 + (size_t)d * 128 + 2 * t);
        u64 w1 = *reinterpret_cast<const u64*>(W1 + (size_t)(d + 1) * 128 + 2 * t);
        ffma2(a1a, dup2(sX[r4][d]), w0);
        ffma2(a1b, dup2(sX[r4][d + 1]), w1);
    }
    {
        float2 y = unpack2(addp2(a1a, a1b));
        sY[r4][2 * t]     = fmaxf(y.x, 0.f);
        sY[r4][2 * t + 1] = fmaxf(y.y, 0.f);
    }
    __syncthreads();

    const int u = t & 31, g = t >> 5;
    u64 a2a = 0, a2b = 0;
    #pragma unroll 16
    for (int f = 0; f < 64; f += 2) {
        u64 w0 = *reinterpret_cast<const u64*>(W2 + (size_t)(g * 64 + f) * 64 + 2 * u);
        u64 w1 = *reinterpret_cast<const u64*>(W2 + (size_t)(g * 64 + f + 1) * 64 + 2 * u);
        ffma2(a2a, dup2(sY[r4][g * 64 + f]), w0);
        ffma2(a2b, dup2(sY[r4][g * 64 + f + 1]), w1);
    }
    float2 p = unpack2(addp2(a2a, a2b));
    if (g == 1) { sPp[r4][2 * u] = p.x; sPp[r4][2 * u + 1] = p.y; }
    __syncthreads();
    if (g == 0) {
        sZ[r4][2 * u]     = p.x + sPp[r4][2 * u]     + b2[2 * u]     + sX[r4][2 * u];
        sZ[r4][2 * u + 1] = p.y + sPp[r4][2 * u + 1] + b2[2 * u + 1] + sX[r4][2 * u + 1];
    }
    __syncthreads();

    if (g == 0) {
        float z0 = sZ[r4][u], z1 = sZ[r4][u + 32];
        float s = z0 + z1, ss = z0 * z0 + z1 * z1;
        #pragma unroll
        for (int off = 16; off > 0; off >>= 1) {
            s  += __shfl_xor_sync(0xffffffffu, s, off);
            ss += __shfl_xor_sync(0xffffffffu, ss, off);
        }
        float mu  = s * (1.f / 64.f);
        float var = ss * (1.f / 64.f) - mu * mu;
        float rs  = rsqrtf(var + EPSV);
        out[row * 64 + u]      = (z0 - mu) * rs * gam[u] + bet[u];
        out[row * 64 + u + 32] = (z1 - mu) * rs * gam[u + 32] + bet[u + 32];
    }
}

// ---------------------------------------------------------------------------
// Launch
// ---------------------------------------------------------------------------
extern "C" void kernel_launch(void* const* d_in, const int* in_sizes, int n_in,
                              void* d_out, int out_size)
{
    const float* seq   = (const float*)d_in[0];
    const float* pos   = (const float*)d_in[1];
    const float* Wq    = (const float*)d_in[2];
    const float* Wk    = (const float*)d_in[3];
    const float* Wv    = (const float*)d_in[4];
    const float* Wo    = (const float*)d_in[5];
    const float* Wp    = (const float*)d_in[6];
    const float* bp    = (const float*)d_in[7];
    const float* W1    = (const float*)d_in[8];
    const float* b1    = (const float*)d_in[9];
    const float* W2    = (const float*)d_in[10];
    const float* b2    = (const float*)d_in[11];
    const float* g_att = (const float*)d_in[12];
    const float* b_att = (const float*)d_in[13];
    const float* g_ff  = (const float*)d_in[14];
    const float* b_ff  = (const float*)d_in[15];
    float* outp = (float*)d_out;

    cudaFuncSetAttribute(attn_kernel, cudaFuncAttributeMaxDynamicSharedMemorySize,
                         ATTN_SMEM_BYTES);
    cudaFuncSetAttribute(proj_ln_kernel, cudaFuncAttributeMaxDynamicSharedMemorySize,
                         PROJ_SMEM_BYTES);

    qkv_kernel<<<dim3(32, 8, 3), 256>>>(seq, Wq, Wk, Wv);
    posbias_kernel<<<dim3(4, 512, 4), 128>>>(pos, Wp, bp);
    attn_kernel<<<dim3(32, 16), 256, ATTN_SMEM_BYTES>>>();
    proj_ln_kernel<<<128, 512, PROJ_SMEM_BYTES>>>(seq, Wo, g_att, b_att);
    ffn_ln_kernel<<<512, 256>>>(W1, b1, W2, b2, g_ff, b_ff, outp);
}

// round 7
// speedup vs baseline: 1.8245x; 1.1220x over previous
#include <cuda_runtime.h>
#include <math.h>

// Problem constants
#define BN   4
#define SN   512
#define DN   64
#define HN   8
#define FFN  128
#define EPSV 1e-5f

typedef unsigned long long u64;
typedef unsigned int u32;

// ---------------------------------------------------------------------------
// Packed fp32x2 helpers (sm_100+)
// ---------------------------------------------------------------------------
__device__ __forceinline__ u64 pack2(float lo, float hi) {
    u64 r; asm("mov.b64 %0, {%1, %2};" : "=l"(r) : "f"(lo), "f"(hi)); return r;
}
__device__ __forceinline__ u64 dup2(float x) {
    u64 r; asm("mov.b64 %0, {%1, %1};" : "=l"(r) : "f"(x)); return r;
}
__device__ __forceinline__ void ffma2(u64& d, u64 a, u64 b) {
    asm("fma.rn.f32x2 %0, %1, %2, %0;" : "+l"(d) : "l"(a), "l"(b));
}
__device__ __forceinline__ u64 addp2(u64 a, u64 b) {
    u64 r; asm("add.rn.f32x2 %0, %1, %2;" : "=l"(r) : "l"(a), "l"(b)); return r;
}
__device__ __forceinline__ float2 unpack2(u64 v) {
    float2 f; asm("mov.b64 {%0, %1}, %2;" : "=f"(f.x), "=f"(f.y) : "l"(v)); return f;
}

// ---------------------------------------------------------------------------
// tf32 MMA helpers (3xTF32 split)
// ---------------------------------------------------------------------------
__device__ __forceinline__ u32 tf32_of(float x) {
    u32 r; asm("cvt.rna.tf32.f32 %0, %1;" : "=r"(r) : "f"(x)); return r;
}
__device__ __forceinline__ void split_tf32(float x, u32& hi, u32& lo) {
    hi = tf32_of(x);
    lo = tf32_of(x - __uint_as_float(hi));
}
__device__ __forceinline__ void mma8(float* d, const u32* a, const u32* b) {
    asm volatile(
        "mma.sync.aligned.m16n8k8.row.col.f32.tf32.tf32.f32 "
        "{%0,%1,%2,%3}, {%4,%5,%6,%7}, {%8,%9}, {%0,%1,%2,%3};"
        : "+f"(d[0]), "+f"(d[1]), "+f"(d[2]), "+f"(d[3])
        : "r"(a[0]), "r"(a[1]), "r"(a[2]), "r"(a[3]), "r"(b[0]), "r"(b[1]));
}

// ---------------------------------------------------------------------------
// Scratch
// ---------------------------------------------------------------------------
__device__ float g_q[BN * HN * SN * DN];
__device__ float g_k[BN * HN * SN * DN];
__device__ float g_v[BN * HN * SN * DN];
__device__ float g_p[(size_t)BN * HN * SN * SN];
__device__ float g_heads[BN * SN * HN * DN];
__device__ float g_po[4][BN * SN * DN];           // proj K-split partials (2MB)

// ---------------------------------------------------------------------------
// Kernel 1: QKV projection (unchanged)
// ---------------------------------------------------------------------------
__global__ __launch_bounds__(256) void qkv_kernel(
    const float* __restrict__ seq, const float* __restrict__ Wq,
    const float* __restrict__ Wk, const float* __restrict__ Wv)
{
    __shared__ float sA[64 * 65];
    __shared__ float sB[64 * 66];
    const int m0   = blockIdx.x * 64;
    const int head = blockIdx.y;
    const float* __restrict__ W =
        (blockIdx.z == 0) ? Wq : (blockIdx.z == 1 ? Wk : Wv);
    float* outB = (blockIdx.z == 0) ? g_q : (blockIdx.z == 1 ? g_k : g_v);
    const int tid = threadIdx.x;

    for (int idx = tid; idx < 64 * 16; idx += 256) {
        int r = idx >> 4, c = (idx & 15) << 2;
        float4 a4 = *reinterpret_cast<const float4*>(seq + (size_t)(m0 + r) * 64 + c);
        sA[r * 65 + c] = a4.x; sA[r * 65 + c + 1] = a4.y;
        sA[r * 65 + c + 2] = a4.z; sA[r * 65 + c + 3] = a4.w;
        float4 b4 = *reinterpret_cast<const float4*>(W + (size_t)r * 512 + head * 64 + c);
        sB[r * 66 + c] = b4.x; sB[r * 66 + c + 1] = b4.y;
        sB[r * 66 + c + 2] = b4.z; sB[r * 66 + c + 3] = b4.w;
    }
    __syncthreads();

    const int ty = tid >> 4, tx = tid & 15;
    u64 acc[4][2] = {};
    #pragma unroll 16
    for (int k = 0; k < 64; k++) {
        u64 b0 = *reinterpret_cast<const u64*>(&sB[k * 66 + tx * 4]);
        u64 b1 = *reinterpret_cast<const u64*>(&sB[k * 66 + tx * 4 + 2]);
        #pragma unroll
        for (int i = 0; i < 4; i++) {
            u64 a = dup2(sA[(ty * 4 + i) * 65 + k]);
            ffma2(acc[i][0], a, b0);
            ffma2(acc[i][1], a, b1);
        }
    }

    const int bb = m0 >> 9;
    const int s0 = m0 & 511;
    #pragma unroll
    for (int i = 0; i < 4; i++) {
        float2 p0 = unpack2(acc[i][0]), p1 = unpack2(acc[i][1]);
        float4 o4 = make_float4(p0.x, p0.y, p1.x, p1.y);
        *reinterpret_cast<float4*>(
            outB + ((size_t)((bb * HN + head) * SN + s0 + ty * 4 + i)) * DN + tx * 4) = o4;
    }
}

// ---------------------------------------------------------------------------
// Kernel 2: positional bias. __ldcs on pos_enc (evict-first) so g_p stays
// L2-resident for attn's re-read.
// ---------------------------------------------------------------------------
__global__ __launch_bounds__(128) void posbias_kernel(
    const float* __restrict__ pos, const float* __restrict__ Wp,
    const float* __restrict__ bp)
{
    __shared__ float sP[128][65];
    __shared__ float sW[64][8];
    __shared__ float sbp[8];
    const int jt  = blockIdx.x;
    const int i   = blockIdx.y;
    const int b   = blockIdx.z;
    const int tid = threadIdx.x;

    for (int idx = tid; idx < 512; idx += 128) sW[idx >> 3][idx & 7] = Wp[idx];
    if (tid < 8) sbp[tid] = bp[tid];

    const float* src = pos + (((size_t)b * SN + i) * SN + jt * 128) * DN;
    #pragma unroll
    for (int it = 0; it < 16; it++) {
        int idx = tid + it * 128;
        int r = idx >> 4, c = (idx & 15) << 2;
        float4 v4 = __ldcs(reinterpret_cast<const float4*>(src + (size_t)r * 64 + c));
        sP[r][c] = v4.x; sP[r][c + 1] = v4.y; sP[r][c + 2] = v4.z; sP[r][c + 3] = v4.w;
    }
    __syncthreads();

    u64 acc[4];
    #pragma unroll
    for (int hp = 0; hp < 4; hp++) acc[hp] = pack2(sbp[2 * hp], sbp[2 * hp + 1]);
    #pragma unroll 16
    for (int d = 0; d < 64; d++) {
        u64 x = dup2(sP[tid][d]);
        #pragma unroll
        for (int hp = 0; hp < 4; hp++) {
            u64 w = *reinterpret_cast<const u64*>(&sW[d][2 * hp]);
            ffma2(acc[hp], x, w);
        }
    }

    const int j = jt * 128 + tid;
    #pragma unroll
    for (int hp = 0; hp < 4; hp++) {
        float2 v = unpack2(acc[hp]);
        g_p[(((size_t)b * HN + 2 * hp) * SN + i) * SN + j]     = v.x;
        g_p[(((size_t)b * HN + 2 * hp + 1) * SN + i) * SN + j] = v.y;
    }
}

// ---------------------------------------------------------------------------
// Kernel 3: attention via tf32 MMA. K/V tiles pre-split into hi/lo smem at
// load time (one cvt chain per element, by all 256 threads) -> MMA loops are
// pure LDS + HMMA. smem: sQ[32][68] | hi[64][72] | lo[64][72] | sS[32][516]
// Phase1 uses row stride 68 inside the 72-stride arrays (both conflict-free).
// ---------------------------------------------------------------------------
#define AT_TI 32
#define QLD   68
#define KLD   68
#define VLD   72
#define SLD   516
#define ATTN_SMEM_FLOATS (AT_TI * QLD + 2 * 64 * VLD + AT_TI * SLD + AT_TI)
#define ATTN_SMEM_BYTES  (ATTN_SMEM_FLOATS * 4)

__global__ __launch_bounds__(256, 2) void attn_kernel()
{
    extern __shared__ float sm[];
    float* sQ   = sm;                      // [32][68]
    float* sKVh = sQ + AT_TI * QLD;        // [64][72] hi (stride 68 in phase1)
    float* sKVl = sKVh + 64 * VLD;         // [64][72] lo
    float* sS   = sKVl + 64 * VLD;         // [32][516]
    float* sInv = sS + AT_TI * SLD;

    const int bh  = blockIdx.x;
    const int i0  = blockIdx.y * AT_TI;
    const int tid = threadIdx.x;
    const int w    = tid >> 5, lane = tid & 31;
    const int mh   = (w & 1) * 16;
    const int nq   = (w >> 1) * 16;
    const int lr   = lane >> 2, lc = lane & 3;

    const float* qsrc = g_q + ((size_t)bh * SN + i0) * DN;
    #pragma unroll
    for (int it = 0; it < 2; it++) {
        int id = tid + it * 256;
        int r = id >> 4, c = (id & 15) << 2;
        float4 v = *reinterpret_cast<const float4*>(qsrc + (size_t)r * 64 + c);
        sQ[r * QLD + c] = v.x; sQ[r * QLD + c + 1] = v.y;
        sQ[r * QLD + c + 2] = v.z; sQ[r * QLD + c + 3] = v.w;
    }
    __syncthreads();

    u32 qh[8][4], ql[8][4];
    #pragma unroll
    for (int k8 = 0; k8 < 8; k8++) {
        float a0 = sQ[(mh + lr) * QLD + k8 * 8 + lc];
        float a1 = sQ[(mh + lr + 8) * QLD + k8 * 8 + lc];
        float a2 = sQ[(mh + lr) * QLD + k8 * 8 + lc + 4];
        float a3 = sQ[(mh + lr + 8) * QLD + k8 * 8 + lc + 4];
        split_tf32(a0, qh[k8][0], ql[k8][0]);
        split_tf32(a1, qh[k8][1], ql[k8][1]);
        split_tf32(a2, qh[k8][2], ql[k8][2]);
        split_tf32(a3, qh[k8][3], ql[k8][3]);
    }
    const float* pbase = g_p + ((size_t)bh * SN + i0) * SN;

    // ---- Phase 1: S = QK^T * 0.125 + P   (K pre-split, stride 68)
    for (int jt = 0; jt < 8; jt++) {
        __syncthreads();
        const float* ksrc = g_k + ((size_t)bh * SN + jt * 64) * DN;
        #pragma unroll
        for (int it = 0; it < 4; it++) {
            int id = tid + it * 256;
            int r = id >> 4, c = (id & 15) << 2;
            float4 v = *reinterpret_cast<const float4*>(ksrc + (size_t)r * 64 + c);
            u32 h0, l0, h1, l1, h2, l2, h3, l3;
            split_tf32(v.x, h0, l0); split_tf32(v.y, h1, l1);
            split_tf32(v.z, h2, l2); split_tf32(v.w, h3, l3);
            *reinterpret_cast<uint4*>(&sKVh[r * KLD + c]) = make_uint4(h0, h1, h2, h3);
            *reinterpret_cast<uint4*>(&sKVl[r * KLD + c]) = make_uint4(l0, l1, l2, l3);
        }
        __syncthreads();

        float D[2][4] = {};
        #pragma unroll
        for (int k8 = 0; k8 < 8; k8++) {
            #pragma unroll
            for (int nt = 0; nt < 2; nt++) {
                int base = (nq + nt * 8 + lr) * KLD + k8 * 8 + lc;
                u32 Bh[2] = { *reinterpret_cast<const u32*>(&sKVh[base]),
                              *reinterpret_cast<const u32*>(&sKVh[base + 4]) };
                u32 Bl[2] = { *reinterpret_cast<const u32*>(&sKVl[base]),
                              *reinterpret_cast<const u32*>(&sKVl[base + 4]) };
                mma8(D[nt], qh[k8], Bh);
                mma8(D[nt], ql[k8], Bh);
                mma8(D[nt], qh[k8], Bl);
            }
        }
        #pragma unroll
        for (int nt = 0; nt < 2; nt++) {
            int col = jt * 64 + nq + nt * 8 + 2 * lc;
            float2 p0 = *reinterpret_cast<const float2*>(pbase + (size_t)(mh + lr) * SN + col);
            float2 p1 = *reinterpret_cast<const float2*>(pbase + (size_t)(mh + lr + 8) * SN + col);
            *reinterpret_cast<float2*>(&sS[(mh + lr) * SLD + col]) =
                make_float2(D[nt][0] * 0.125f + p0.x, D[nt][1] * 0.125f + p0.y);
            *reinterpret_cast<float2*>(&sS[(mh + lr + 8) * SLD + col]) =
                make_float2(D[nt][2] * 0.125f + p1.x, D[nt][3] * 0.125f + p1.y);
        }
    }
    __syncthreads();

    // ---- Phase 2: softmax
    #pragma unroll
    for (int rr = 0; rr < 4; rr++) {
        int r = w * 4 + rr;
        float* row = sS + r * SLD;
        float mx = -1e30f;
        #pragma unroll
        for (int c = 0; c < 16; c++) mx = fmaxf(mx, row[lane + c * 32]);
        #pragma unroll
        for (int off = 16; off > 0; off >>= 1)
            mx = fmaxf(mx, __shfl_xor_sync(0xffffffffu, mx, off));
        float sum = 0.f;
        #pragma unroll
        for (int c = 0; c < 16; c++) {
            float e = __expf(row[lane + c * 32] - mx);
            row[lane + c * 32] = e;
            sum += e;
        }
        #pragma unroll
        for (int off = 16; off > 0; off >>= 1)
            sum += __shfl_xor_sync(0xffffffffu, sum, off);
        if (lane == 0) sInv[r] = 1.f / sum;
    }
    __syncthreads();

    // ---- Phase 3: O = A @ V   (V pre-split, stride 72)
    float O[2][4] = {};
    for (int jt = 0; jt < 8; jt++) {
        __syncthreads();
        const float* vsrc = g_v + ((size_t)bh * SN + jt * 64) * DN;
        #pragma unroll
        for (int it = 0; it < 4; it++) {
            int id = tid + it * 256;
            int r = id >> 4, c = (id & 15) << 2;
            float4 v = *reinterpret_cast<const float4*>(vsrc + (size_t)r * 64 + c);
            u32 h0, l0, h1, l1, h2, l2, h3, l3;
            split_tf32(v.x, h0, l0); split_tf32(v.y, h1, l1);
            split_tf32(v.z, h2, l2); split_tf32(v.w, h3, l3);
            *reinterpret_cast<uint4*>(&sKVh[r * VLD + c]) = make_uint4(h0, h1, h2, h3);
            *reinterpret_cast<uint4*>(&sKVl[r * VLD + c]) = make_uint4(l0, l1, l2, l3);
        }
        __syncthreads();

        #pragma unroll
        for (int k8 = 0; k8 < 8; k8++) {
            int kk = jt * 64 + k8 * 8;
            float a0 = sS[(mh + lr) * SLD + kk + lc];
            float a1 = sS[(mh + lr + 8) * SLD + kk + lc];
            float a2 = sS[(mh + lr) * SLD + kk + lc + 4];
            float a3 = sS[(mh + lr + 8) * SLD + kk + lc + 4];
            u32 Ah[4], Al[4];
            split_tf32(a0, Ah[0], Al[0]);
            split_tf32(a1, Ah[1], Al[1]);
            split_tf32(a2, Ah[2], Al[2]);
            split_tf32(a3, Ah[3], Al[3]);
            #pragma unroll
            for (int nt = 0; nt < 2; nt++) {
                int b0i = (k8 * 8 + lc) * VLD + nq + nt * 8 + lr;
                int b1i = (k8 * 8 + lc + 4) * VLD + nq + nt * 8 + lr;
                u32 Bh[2] = { *reinterpret_cast<const u32*>(&sKVh[b0i]),
                              *reinterpret_cast<const u32*>(&sKVh[b1i]) };
                u32 Bl[2] = { *reinterpret_cast<const u32*>(&sKVl[b0i]),
                              *reinterpret_cast<const u32*>(&sKVl[b1i]) };
                mma8(O[nt], Ah, Bh);
                mma8(O[nt], Al, Bh);
                mma8(O[nt], Ah, Bl);
            }
        }
    }

    const int b_ = bh >> 3, h_ = bh & 7;
    float inv0 = sInv[mh + lr], inv1 = sInv[mh + lr + 8];
    #pragma unroll
    for (int nt = 0; nt < 2; nt++) {
        int col = h_ * 64 + nq + nt * 8 + 2 * lc;
        float* o0 = g_heads + ((size_t)(b_ * SN + i0 + mh + lr)) * (HN * DN) + col;
        float* o1 = g_heads + ((size_t)(b_ * SN + i0 + mh + lr + 8)) * (HN * DN) + col;
        *reinterpret_cast<float2*>(o0) = make_float2(O[nt][0] * inv0, O[nt][1] * inv0);
        *reinterpret_cast<float2*>(o1) = make_float2(O[nt][2] * inv1, O[nt][3] * inv1);
    }
}

// ---------------------------------------------------------------------------
// Kernel 4a: proj split-K. grid (32 m-tiles, 4 k-splits), qkv-style 64x64
// tiles, K-chunk 128 (2 sub-chunks of 64). Partials -> g_po[ks].
// ---------------------------------------------------------------------------
__global__ __launch_bounds__(256) void proj_split_kernel(const float* __restrict__ Wo)
{
    __shared__ float sA[64 * 65];
    __shared__ float sB[64 * 66];
    const int m0 = blockIdx.x * 64;
    const int k0 = blockIdx.y * 128;
    const int tid = threadIdx.x;
    const int ty = tid >> 4, tx = tid & 15;

    u64 acc[4][2] = {};
    for (int kc = 0; kc < 2; kc++) {
        if (kc) __syncthreads();
        const int kb = k0 + kc * 64;
        for (int idx = tid; idx < 64 * 16; idx += 256) {
            int r = idx >> 4, c = (idx & 15) << 2;
            float4 a4 = *reinterpret_cast<const float4*>(
                g_heads + (size_t)(m0 + r) * 512 + kb + c);
            sA[r * 65 + c] = a4.x; sA[r * 65 + c + 1] = a4.y;
            sA[r * 65 + c + 2] = a4.z; sA[r * 65 + c + 3] = a4.w;
            float4 b4 = *reinterpret_cast<const float4*>(
                Wo + (size_t)(kb + r) * 64 + c);
            sB[r * 66 + c] = b4.x; sB[r * 66 + c + 1] = b4.y;
            sB[r * 66 + c + 2] = b4.z; sB[r * 66 + c + 3] = b4.w;
        }
        __syncthreads();
        #pragma unroll 16
        for (int k = 0; k < 64; k++) {
            u64 b0 = *reinterpret_cast<const u64*>(&sB[k * 66 + tx * 4]);
            u64 b1 = *reinterpret_cast<const u64*>(&sB[k * 66 + tx * 4 + 2]);
            #pragma unroll
            for (int i = 0; i < 4; i++) {
                u64 a = dup2(sA[(ty * 4 + i) * 65 + k]);
                ffma2(acc[i][0], a, b0);
                ffma2(acc[i][1], a, b1);
            }
        }
    }

    float* outp = g_po[blockIdx.y];
    #pragma unroll
    for (int i = 0; i < 4; i++) {
        float2 p0 = unpack2(acc[i][0]), p1 = unpack2(acc[i][1]);
        float4 o4 = make_float4(p0.x, p0.y, p1.x, p1.y);
        *reinterpret_cast<float4*>(outp + (size_t)(m0 + ty * 4 + i) * 64 + tx * 4) = o4;
    }
}

// ---------------------------------------------------------------------------
// Kernel 4b: x = LN1(seq + sum partials); y = relu(x@W1+b1)@W2+b2;
// out = LN2(x+y). 4 rows/block.
// ---------------------------------------------------------------------------
__global__ __launch_bounds__(256) void ffn_ln_kernel(
    const float* __restrict__ seq,
    const float* __restrict__ W1, const float* __restrict__ b1,
    const float* __restrict__ W2, const float* __restrict__ b2,
    const float* __restrict__ gam1, const float* __restrict__ bet1,
    const float* __restrict__ gam2, const float* __restrict__ bet2,
    float* __restrict__ out)
{
    __shared__ float sRes[4][64];
    __shared__ float sX[4][64];
    __shared__ float sY[4][128];
    __shared__ float sPp[4][64];
    __shared__ float sZ[4][64];
    const int tid  = threadIdx.x;
    const int r4   = tid >> 6;
    const int t    = tid & 63;
    const size_t row = (size_t)blockIdx.x * 4 + r4;
    const size_t ro = row * 64 + t;

    sRes[r4][t] = seq[ro] + g_po[0][ro] + g_po[1][ro] + g_po[2][ro] + g_po[3][ro];
    __syncthreads();

    const int u = t & 31, g = t >> 5;
    if (g == 0) {   // LN1: one full warp per row
        float z0 = sRes[r4][u], z1 = sRes[r4][u + 32];
        float s = z0 + z1, ss = z0 * z0 + z1 * z1;
        #pragma unroll
        for (int off = 16; off > 0; off >>= 1) {
            s  += __shfl_xor_sync(0xffffffffu, s, off);
            ss += __shfl_xor_sync(0xffffffffu, ss, off);
        }
        float mu  = s * (1.f / 64.f);
        float var = ss * (1.f / 64.f) - mu * mu;
        float rs  = rsqrtf(var + EPSV);
        sX[r4][u]      = (z0 - mu) * rs * gam1[u] + bet1[u];
        sX[r4][u + 32] = (z1 - mu) * rs * gam1[u + 32] + bet1[u + 32];
    }
    __syncthreads();

    u64 a1a = *reinterpret_cast<const u64*>(b1 + 2 * t), a1b = 0;
    #pragma unroll 16
    for (int d = 0; d < 64; d += 2) {
        u64 w0 = *reinterpret_cast<const u64*>(W1 + (size_t)d * 128 + 2 * t);
        u64 w1 = *reinterpret_cast<const u64*>(W1 + (size_t)(d + 1) * 128 + 2 * t);
        ffma2(a1a, dup2(sX[r4][d]), w0);
        ffma2(a1b, dup2(sX[r4][d + 1]), w1);
    }
    {
        float2 y = unpack2(addp2(a1a, a1b));
        sY[r4][2 * t]     = fmaxf(y.x, 0.f);
        sY[r4][2 * t + 1] = fmaxf(y.y, 0.f);
    }
    __syncthreads();

    u64 a2a = 0, a2b = 0;
    #pragma unroll 16
    for (int f = 0; f < 64; f += 2) {
        u64 w0 = *reinterpret_cast<const u64*>(W2 + (size_t)(g * 64 + f) * 64 + 2 * u);
        u64 w1 = *reinterpret_cast<const u64*>(W2 + (size_t)(g * 64 + f + 1) * 64 + 2 * u);
        ffma2(a2a, dup2(sY[r4][g * 64 + f]), w0);
        ffma2(a2b, dup2(sY[r4][g * 64 + f + 1]), w1);
    }
    float2 p = unpack2(addp2(a2a, a2b));
    if (g == 1) { sPp[r4][2 * u] = p.x; sPp[r4][2 * u + 1] = p.y; }
    __syncthreads();
    if (g == 0) {
        sZ[r4][2 * u]     = p.x + sPp[r4][2 * u]     + b2[2 * u]     + sX[r4][2 * u];
        sZ[r4][2 * u + 1] = p.y + sPp[r4][2 * u + 1] + b2[2 * u + 1] + sX[r4][2 * u + 1];
    }
    __syncthreads();

    if (g == 0) {
        float z0 = sZ[r4][u], z1 = sZ[r4][u + 32];
        float s = z0 + z1, ss = z0 * z0 + z1 * z1;
        #pragma unroll
        for (int off = 16; off > 0; off >>= 1) {
            s  += __shfl_xor_sync(0xffffffffu, s, off);
            ss += __shfl_xor_sync(0xffffffffu, ss, off);
        }
        float mu  = s * (1.f / 64.f);
        float var = ss * (1.f / 64.f) - mu * mu;
        float rs  = rsqrtf(var + EPSV);
        out[row * 64 + u]      = (z0 - mu) * rs * gam2[u] + bet2[u];
        out[row * 64 + u + 32] = (z1 - mu) * rs * gam2[u + 32] + bet2[u + 32];
    }
}

// ---------------------------------------------------------------------------
// Launch
// ---------------------------------------------------------------------------
extern "C" void kernel_launch(void* const* d_in, const int* in_sizes, int n_in,
                              void* d_out, int out_size)
{
    const float* seq   = (const float*)d_in[0];
    const float* pos   = (const float*)d_in[1];
    const float* Wq    = (const float*)d_in[2];
    const float* Wk    = (const float*)d_in[3];
    const float* Wv    = (const float*)d_in[4];
    const float* Wo    = (const float*)d_in[5];
    const float* Wp    = (const float*)d_in[6];
    const float* bp    = (const float*)d_in[7];
    const float* W1    = (const float*)d_in[8];
    const float* b1    = (const float*)d_in[9];
    const float* W2    = (const float*)d_in[10];
    const float* b2    = (const float*)d_in[11];
    const float* g_att = (const float*)d_in[12];
    const float* b_att = (const float*)d_in[13];
    const float* g_ff  = (const float*)d_in[14];
    const float* b_ff  = (const float*)d_in[15];
    float* outp = (float*)d_out;

    cudaFuncSetAttribute(attn_kernel, cudaFuncAttributeMaxDynamicSharedMemorySize,
                         ATTN_SMEM_BYTES);

    qkv_kernel<<<dim3(32, 8, 3), 256>>>(seq, Wq, Wk, Wv);
    posbias_kernel<<<dim3(4, 512, 4), 128>>>(pos, Wp, bp);
    attn_kernel<<<dim3(32, 16), 256, ATTN_SMEM_BYTES>>>();
    proj_split_kernel<<<dim3(32, 4), 256>>>(Wo);
    ffn_ln_kernel<<<512, 256>>>(seq, W1, b1, W2, b2, g_att, b_att, g_ff, b_ff, outp);
}